// round 4
// baseline (speedup 1.0000x reference)
#include <cuda_runtime.h>
#include <cuda_bf16.h>
#include <cstdint>

// Problem constants: B=2, S=2048, D=1024, H=16, HD=64
#define BB   2
#define SS   2048
#define DD   1024
#define HH   16
#define HD   64
#define MDIM (BB*SS)     // 4096
#define KD   DD          // 1024

// Scratch (allocation-free rule: __device__ globals). All tf32 bit patterns.
__device__ uint32_t g_x32[MDIM*KD];        // x, k-permuted
__device__ uint32_t g_w32[4][DD*KD];       // qw,kw,vw,ow, k-permuted
__device__ uint32_t g_q32[BB*HH*SS*HD];    // [B,H,S,HD], hd-permuted
__device__ uint32_t g_k32[BB*HH*SS*HD];
__device__ uint32_t g_v32[BB*HH*SS*HD];
__device__ uint32_t g_attn32[BB*SS*DD];    // [B,S,D], d-permuted

// ---------------------------------------------------------------------------
// helpers
// ---------------------------------------------------------------------------
__device__ __forceinline__ uint32_t f2tf(float x) {
    uint32_t r;
    asm("cvt.rna.tf32.f32 %0, %1;" : "=r"(r) : "f"(x));
    return r;
}
// pair permutation within 8-blocks: p(c), p(c+4) adjacent for c%8<4
__device__ __forceinline__ int permf(int c)  { return (c & ~7) | ((c & 3) << 1) | ((c & 4) >> 2); }
__device__ __forceinline__ int permi(int j)  { return (j & ~7) | ((j >> 1) & 3) | ((j & 1) << 2); }

__device__ __forceinline__ void mma_tf32(float* c, const uint32_t* a, const uint32_t* b) {
    asm volatile(
        "mma.sync.aligned.m16n8k8.row.col.f32.tf32.tf32.f32 "
        "{%0,%1,%2,%3}, {%4,%5,%6,%7}, {%8,%9}, {%0,%1,%2,%3};"
        : "+f"(c[0]), "+f"(c[1]), "+f"(c[2]), "+f"(c[3])
        : "r"(a[0]), "r"(a[1]), "r"(a[2]), "r"(a[3]),
          "r"(b[0]), "r"(b[1]));
}

__device__ __forceinline__ void cpa16(void* smem, const void* g) {
    uint32_t s = (uint32_t)__cvta_generic_to_shared(smem);
    asm volatile("cp.async.cg.shared.global [%0], [%1], 16;" :: "r"(s), "l"(g) : "memory");
}

// ---------------------------------------------------------------------------
// prep: fp32 -> tf32 bits with k-dim pair-permutation. 8192 rows x 1024.
// rows 0-4095: x; then qw, kw, vw, ow (1024 rows each).
// ---------------------------------------------------------------------------
__global__ void __launch_bounds__(256) prep_tf32(const float* __restrict__ x,
                                                 const float* __restrict__ qw,
                                                 const float* __restrict__ kw,
                                                 const float* __restrict__ vw,
                                                 const float* __restrict__ ow)
{
    const int idx = blockIdx.x * 256 + threadIdx.x;   // 0 .. 2M-1
    const int row = idx >> 8;
    const int j0  = (idx & 255) << 2;

    const float* src;
    uint32_t*    dst;
    if (row < MDIM) {
        src = x + (size_t)row * KD;
        dst = g_x32 + (size_t)row * KD;
    } else {
        const int w = (row - MDIM) >> 10;
        const int r = (row - MDIM) & 1023;
        const float* ws = (w == 0) ? qw : (w == 1) ? kw : (w == 2) ? vw : ow;
        src = ws + (size_t)r * KD;
        dst = g_w32[w] + (size_t)r * KD;
    }
    uint4 o;
    o.x = f2tf(src[permi(j0 + 0)]);
    o.y = f2tf(src[permi(j0 + 1)]);
    o.z = f2tf(src[permi(j0 + 2)]);
    o.w = f2tf(src[permi(j0 + 3)]);
    *(uint4*)(dst + j0) = o;
}

// ---------------------------------------------------------------------------
// TF32 tensor-core GEMM on pre-converted, k-permuted uint32 operands.
// C[m,n] = sum_k A[m,k]*W[n,k] + bias[n].
// outmode 0/1/2: A=g_x32, W=g_w32[o], scatter tf32 bits into q/k/v (hd permuted)
// outmode 3:     A=g_attn32, W=g_w32[3], write fp32 to Cext.
// ---------------------------------------------------------------------------
#define PADK 20

__global__ void __launch_bounds__(256) gemm_tc32(const float* __restrict__ bias,
                                                 float* __restrict__ Cext,
                                                 int outmode)
{
    __shared__ uint32_t sA[2][128 * PADK];
    __shared__ uint32_t sW[2][128 * PADK];

    const int t    = threadIdx.x;
    const int lane = t & 31;
    const int warp = t >> 5;
    const int wm   = warp & 3;
    const int wn   = warp >> 2;
    const int m0   = blockIdx.y * 128;
    const int n0   = blockIdx.x * 128;

    const uint32_t* A = (outmode == 3) ? g_attn32 : g_x32;
    const uint32_t* W = g_w32[outmode];

    float c[2][8][4];
#pragma unroll
    for (int mt = 0; mt < 2; mt++)
#pragma unroll
        for (int nt = 0; nt < 8; nt++)
#pragma unroll
            for (int i = 0; i < 4; i++) c[mt][nt][i] = 0.f;

    auto issue = [&](int kt, int buf) {
        const int k0 = kt * 16;
#pragma unroll
        for (int i = 0; i < 2; i++) {
            const int idx = t + i * 256;
            const int row = idx >> 2;
            const int c4  = (idx & 3) << 2;
            cpa16(&sA[buf][row * PADK + c4], A + (size_t)(m0 + row) * KD + k0 + c4);
            cpa16(&sW[buf][row * PADK + c4], W + (size_t)(n0 + row) * KD + k0 + c4);
        }
        asm volatile("cp.async.commit_group;" ::: "memory");
    };

    issue(0, 0);
    const int NK = KD / 16;

    const int g  = lane >> 2;
    const int kq = lane & 3;

    for (int kt = 0; kt < NK; kt++) {
        asm volatile("cp.async.wait_group 0;" ::: "memory");
        __syncthreads();
        if (kt + 1 < NK) issue(kt + 1, (kt + 1) & 1);

        const uint32_t* a = &sA[kt & 1][0];
        const uint32_t* w = &sW[kt & 1][0];

#pragma unroll
        for (int ks = 0; ks < 2; ks++) {
            const int kk = ks * 8 + (kq << 1);   // permuted (k, k+4) pair base
            uint32_t af[2][4], bf[8][2];
#pragma unroll
            for (int mt = 0; mt < 2; mt++) {
                const int rb = wm * 32 + mt * 16 + g;
                uint2 v0 = *(const uint2*)&a[rb * PADK + kk];
                uint2 v1 = *(const uint2*)&a[(rb + 8) * PADK + kk];
                af[mt][0] = v0.x; af[mt][1] = v1.x; af[mt][2] = v0.y; af[mt][3] = v1.y;
            }
#pragma unroll
            for (int nt = 0; nt < 8; nt++) {
                const int nb = wn * 64 + nt * 8 + g;
                uint2 v = *(const uint2*)&w[nb * PADK + kk];
                bf[nt][0] = v.x; bf[nt][1] = v.y;
            }
#pragma unroll
            for (int mt = 0; mt < 2; mt++)
#pragma unroll
                for (int nt = 0; nt < 8; nt++)
                    mma_tf32(c[mt][nt], af[mt], bf[nt]);
        }
        __syncthreads();
    }

    if (outmode < 3) {
        uint32_t* dst = (outmode == 0) ? g_q32 : (outmode == 1) ? g_k32 : g_v32;
#pragma unroll
        for (int mt = 0; mt < 2; mt++) {
            const int r0 = m0 + wm * 32 + mt * 16 + g;
#pragma unroll
            for (int nt = 0; nt < 8; nt++) {
                const int n  = n0 + wn * 64 + nt * 8 + (kq << 1);
                const float b0 = bias[n], b1 = bias[n + 1];
                const int h   = n >> 6;
                const int hd0 = permf(n & 63);
                const int hd1 = permf((n + 1) & 63);
#pragma unroll
                for (int half = 0; half < 2; half++) {
                    const int r = r0 + half * 8;
                    const int b = r >> 11;
                    const int s = r & (SS - 1);
                    const size_t base = (((size_t)(b * HH + h)) * SS + s) * HD;
                    dst[base + hd0] = f2tf(c[mt][nt][half * 2 + 0] + b0);
                    dst[base + hd1] = f2tf(c[mt][nt][half * 2 + 1] + b1);
                }
            }
        }
    } else {
#pragma unroll
        for (int mt = 0; mt < 2; mt++) {
            const int r0 = m0 + wm * 32 + mt * 16 + g;
#pragma unroll
            for (int nt = 0; nt < 8; nt++) {
                const int n  = n0 + wn * 64 + nt * 8 + (kq << 1);
                const float b0 = bias[n], b1 = bias[n + 1];
#pragma unroll
                for (int half = 0; half < 2; half++) {
                    const int r = r0 + half * 8;
                    float2* p = (float2*)&Cext[(size_t)r * DD + n];
                    *p = make_float2(c[mt][nt][half * 2 + 0] + b0,
                                     c[mt][nt][half * 2 + 1] + b1);
                }
            }
        }
    }
}

// ---------------------------------------------------------------------------
// TF32 tensor-core causal flash attention, pre-converted operands.
// Grid: (S/128 q-tiles, B*H). Block: 256 threads = 8 warps x 16 q-rows.
// ---------------------------------------------------------------------------
__global__ void __launch_bounds__(256) attn_tc32()
{
    __shared__ uint32_t Ks[64 * 64];
    __shared__ uint32_t Vs[64 * 64];

    const int bh   = blockIdx.y;
    const int qt   = (gridDim.x - 1) - blockIdx.x;  // heavy tiles first
    const int tid  = threadIdx.x;
    const int lane = tid & 31;
    const int warp = tid >> 5;      // 0..7
    const int g    = lane >> 2;
    const int kq   = lane & 3;

    const uint32_t* Qb = g_q32 + (size_t)bh * SS * HD;
    const uint32_t* Kb = g_k32 + (size_t)bh * SS * HD;
    const uint32_t* Vb = g_v32 + (size_t)bh * SS * HD;

    // ---- stage Q tile (128x64) into Ks(rows 0-63) + Vs(rows 64-127) ----
    {
        const uint32_t* Qs = Qb + (size_t)qt * 128 * HD;
#pragma unroll
        for (int i = 0; i < 8; i++) {
            const int idx = tid + i * 256;       // 0..2047 uint4s
            const int rr  = idx >> 4;
            const int cc  = (idx & 15) << 2;
            uint4 f = *(const uint4*)(Qs + idx * 4);
            uint32_t* d = (rr < 64) ? Ks : Vs;
            *(uint4*)&d[(rr & 63) * 64 + (cc ^ ((rr & 7) << 2))] = f;
        }
    }
    __syncthreads();

    const int r0 = warp * 16 + g;      // q-row in tile (and r0+8)
    uint32_t qf[8][4];
    {
        const uint32_t* Qt = (warp < 4) ? Ks : Vs;
        const int rr0 = r0 & 63, rr1 = rr0 + 8;
        const int sw  = g << 2;
#pragma unroll
        for (int ks = 0; ks < 8; ks++) {
            const int kk = ks * 8 + (kq << 1);
            uint2 v0 = *(const uint2*)&Qt[rr0 * 64 + (kk ^ sw)];
            uint2 v1 = *(const uint2*)&Qt[rr1 * 64 + (kk ^ sw)];
            qf[ks][0] = v0.x; qf[ks][1] = v1.x; qf[ks][2] = v0.y; qf[ks][3] = v1.y;
        }
    }
    __syncthreads();

    float acc[8][4];
#pragma unroll
    for (int nt = 0; nt < 8; nt++)
#pragma unroll
        for (int i = 0; i < 4; i++) acc[nt][i] = 0.f;
    float m0 = -1e30f, m1 = -1e30f, l0 = 0.f, l1 = 0.f;
    const float scale = 0.125f;

    const int rowg0 = qt * 128 + r0;           // global q row (and +8)
    const int wmax  = qt * 128 + warp * 16 + 15;
    const int NT    = 2 * qt + 2;

    for (int kv = 0; kv < NT; kv++) {
        __syncthreads();
        {
            const uint32_t* Kp = Kb + (size_t)kv * 64 * HD;
            const uint32_t* Vp = Vb + (size_t)kv * 64 * HD;
#pragma unroll
            for (int i = 0; i < 4; i++) {
                const int idx = tid + i * 256;   // 0..1023
                const int rr  = idx >> 4;
                const int cc  = (idx & 15) << 2;
                const int sa  = rr * 64 + (cc ^ ((rr & 7) << 2));
                *(uint4*)&Ks[sa] = *(const uint4*)(Kp + idx * 4);
                *(uint4*)&Vs[sa] = *(const uint4*)(Vp + idx * 4);
            }
        }
        __syncthreads();

        if (kv * 64 > wmax) continue;   // tile fully above diagonal for this warp

        // ---- S = Q @ K^T ----
        float c[8][4];
#pragma unroll
        for (int nt = 0; nt < 8; nt++)
#pragma unroll
            for (int i = 0; i < 4; i++) c[nt][i] = 0.f;

#pragma unroll
        for (int ks = 0; ks < 8; ks++) {
            const int kk = ks * 8 + (kq << 1);
#pragma unroll
            for (int nt = 0; nt < 8; nt++) {
                const int krow = nt * 8 + g;
                uint2 v = *(const uint2*)&Ks[krow * 64 + (kk ^ (g << 2))];
                uint32_t b[2] = {v.x, v.y};
                mma_tf32(c[nt], qf[ks], b);
            }
        }

        // ---- scale + causal mask ----
        const bool needmask = (kv * 64 + 63) > (qt * 128 + warp * 16);
#pragma unroll
        for (int nt = 0; nt < 8; nt++) {
#pragma unroll
            for (int i = 0; i < 4; i++) {
                float v = c[nt][i] * scale;
                if (needmask) {
                    const int col = kv * 64 + nt * 8 + (kq << 1) + (i & 1);
                    const int row = rowg0 + ((i & 2) << 2);
                    if (col > row) v = -1e30f;
                }
                c[nt][i] = v;
            }
        }

        // ---- online softmax ----
        float t0 = -1e30f, t1 = -1e30f;
#pragma unroll
        for (int nt = 0; nt < 8; nt++) {
            t0 = fmaxf(t0, fmaxf(c[nt][0], c[nt][1]));
            t1 = fmaxf(t1, fmaxf(c[nt][2], c[nt][3]));
        }
        t0 = fmaxf(t0, __shfl_xor_sync(0xffffffffu, t0, 1));
        t0 = fmaxf(t0, __shfl_xor_sync(0xffffffffu, t0, 2));
        t1 = fmaxf(t1, __shfl_xor_sync(0xffffffffu, t1, 1));
        t1 = fmaxf(t1, __shfl_xor_sync(0xffffffffu, t1, 2));

        const float mn0 = fmaxf(m0, t0);
        const float mn1 = fmaxf(m1, t1);
        const float a0  = __expf(m0 - mn0);
        const float a1  = __expf(m1 - mn1);

        float s0 = 0.f, s1 = 0.f;
#pragma unroll
        for (int nt = 0; nt < 8; nt++) {
            c[nt][0] = __expf(c[nt][0] - mn0);
            c[nt][1] = __expf(c[nt][1] - mn0);
            c[nt][2] = __expf(c[nt][2] - mn1);
            c[nt][3] = __expf(c[nt][3] - mn1);
            s0 += c[nt][0] + c[nt][1];
            s1 += c[nt][2] + c[nt][3];
        }
        s0 += __shfl_xor_sync(0xffffffffu, s0, 1);
        s0 += __shfl_xor_sync(0xffffffffu, s0, 2);
        s1 += __shfl_xor_sync(0xffffffffu, s1, 1);
        s1 += __shfl_xor_sync(0xffffffffu, s1, 2);

        l0 = l0 * a0 + s0;  m0 = mn0;
        l1 = l1 * a1 + s1;  m1 = mn1;

#pragma unroll
        for (int nt = 0; nt < 8; nt++) {
            acc[nt][0] *= a0; acc[nt][1] *= a0;
            acc[nt][2] *= a1; acc[nt][3] *= a1;
        }

        // ---- O += P @ V (P: C-layout -> A-layout via shuffles) ----
        const int src1 = (lane & ~3) | (kq >> 1);
        const int src2 = src1 + 2;
#pragma unroll
        for (int ks = 0; ks < 8; ks++) {
            const float x0 = __shfl_sync(0xffffffffu, c[ks][0], src1);
            const float x1 = __shfl_sync(0xffffffffu, c[ks][1], src1);
            const float y0 = __shfl_sync(0xffffffffu, c[ks][0], src2);
            const float y1 = __shfl_sync(0xffffffffu, c[ks][1], src2);
            const float z0 = __shfl_sync(0xffffffffu, c[ks][2], src1);
            const float z1 = __shfl_sync(0xffffffffu, c[ks][3], src1);
            const float w0 = __shfl_sync(0xffffffffu, c[ks][2], src2);
            const float w1 = __shfl_sync(0xffffffffu, c[ks][3], src2);
            uint32_t pa[4];
            pa[0] = f2tf((kq & 1) ? x1 : x0);
            pa[1] = f2tf((kq & 1) ? z1 : z0);
            pa[2] = f2tf((kq & 1) ? y1 : y0);
            pa[3] = f2tf((kq & 1) ? w1 : w0);

            const int vr0 = ks * 8 + kq;
            const int vr1 = vr0 + 4;
            const int sw0 = kq << 2;
            const int sw1 = (kq + 4) << 2;
#pragma unroll
            for (int nt = 0; nt < 8; nt++) {
                const int vc = nt * 8 + g;
                uint32_t b[2];
                b[0] = Vs[vr0 * 64 + (vc ^ sw0)];
                b[1] = Vs[vr1 * 64 + (vc ^ sw1)];
                mma_tf32(acc[nt], pa, b);
            }
        }
    }

    // ---- finalize: normalize, store tf32 bits to g_attn32 (d-permuted) ----
    const int b = bh >> 4, h = bh & 15;
    const float inv0 = 1.f / l0;
    const float inv1 = 1.f / l1;
    const int qr0 = qt * 128 + r0;
    const int qr1 = qr0 + 8;
#pragma unroll
    for (int nt = 0; nt < 8; nt++) {
        const int col = h * HD + nt * 8 + (kq << 1);
        uint32_t* p0 = &g_attn32[((size_t)(b * SS + qr0)) * DD + col];
        uint32_t* p1 = &g_attn32[((size_t)(b * SS + qr1)) * DD + col];
        p0[0] = f2tf(acc[nt][0] * inv0);
        p0[1] = f2tf(acc[nt][1] * inv0);
        p1[0] = f2tf(acc[nt][2] * inv1);
        p1[1] = f2tf(acc[nt][3] * inv1);
    }
}

// ---------------------------------------------------------------------------
extern "C" void kernel_launch(void* const* d_in, const int* in_sizes, int n_in,
                              void* d_out, int out_size)
{
    const float* x  = (const float*)d_in[0];
    const float* qw = (const float*)d_in[1];
    const float* qb = (const float*)d_in[2];
    const float* kw = (const float*)d_in[3];
    const float* kb = (const float*)d_in[4];
    const float* vw = (const float*)d_in[5];
    const float* vb = (const float*)d_in[6];
    const float* ow = (const float*)d_in[7];
    const float* ob = (const float*)d_in[8];
    float* out = (float*)d_out;

    prep_tf32<<<(MDIM + 4 * DD) * (KD / 4) / 256, 256>>>(x, qw, kw, vw, ow);

    dim3 gblk(256);
    dim3 ggrd(DD / 128, MDIM / 128);   // (8, 32)

    gemm_tc32<<<ggrd, gblk>>>(qb, nullptr, 0);
    gemm_tc32<<<ggrd, gblk>>>(kb, nullptr, 1);
    gemm_tc32<<<ggrd, gblk>>>(vb, nullptr, 2);

    attn_tc32<<<dim3(SS / 128, BB * HH), 256>>>();

    gemm_tc32<<<ggrd, gblk>>>(ob, out, 3);
}

// round 5
// speedup vs baseline: 1.8059x; 1.8059x over previous
#include <cuda_runtime.h>
#include <cuda_bf16.h>
#include <cstdint>

// Problem constants: B=2, S=2048, D=1024, H=16, HD=64
#define BB   2
#define SS   2048
#define DD   1024
#define HH   16
#define HD   64
#define MDIM (BB*SS)     // 4096
#define KD   DD          // 1024

// Scratch (allocation-free rule: __device__ globals). tf32 bit patterns, PLAIN layout.
__device__ uint32_t g_x32[MDIM*KD];
__device__ uint32_t g_w32[4][DD*KD];       // qw,kw,vw,ow
__device__ uint32_t g_q32[BB*HH*SS*HD];    // [B,H,S,HD]
__device__ uint32_t g_k32[BB*HH*SS*HD];
__device__ uint32_t g_v32[BB*HH*SS*HD];
__device__ uint32_t g_attn32[BB*SS*DD];    // [B,S,D]

// ---------------------------------------------------------------------------
// helpers
// ---------------------------------------------------------------------------
__device__ __forceinline__ uint32_t f2tf(float x) {
    uint32_t r;
    asm("cvt.rna.tf32.f32 %0, %1;" : "=r"(r) : "f"(x));
    return r;
}

__device__ __forceinline__ void mma_tf32(float* c, const uint32_t* a, const uint32_t* b) {
    asm volatile(
        "mma.sync.aligned.m16n8k8.row.col.f32.tf32.tf32.f32 "
        "{%0,%1,%2,%3}, {%4,%5,%6,%7}, {%8,%9}, {%0,%1,%2,%3};"
        : "+f"(c[0]), "+f"(c[1]), "+f"(c[2]), "+f"(c[3])
        : "r"(a[0]), "r"(a[1]), "r"(a[2]), "r"(a[3]),
          "r"(b[0]), "r"(b[1]));
}

__device__ __forceinline__ void cpa16(void* smem, const void* g) {
    uint32_t s = (uint32_t)__cvta_generic_to_shared(smem);
    asm volatile("cp.async.cg.shared.global [%0], [%1], 16;" :: "r"(s), "l"(g) : "memory");
}

// ---------------------------------------------------------------------------
// prep: fp32 -> tf32 bits, PLAIN layout (no permutation).
// rows 0..4095: x; then qw,kw,vw,ow (1024 rows each). One uint4 per thread.
// ---------------------------------------------------------------------------
__global__ void __launch_bounds__(256) prep_tf32(const float* __restrict__ x,
                                                 const float* __restrict__ qw,
                                                 const float* __restrict__ kw,
                                                 const float* __restrict__ vw,
                                                 const float* __restrict__ ow)
{
    const int idx = blockIdx.x * 256 + threadIdx.x;   // 0 .. 2M-1
    const int row = idx >> 8;          // 256 uint4 per 1024-wide row
    const int j0  = (idx & 255) << 2;

    const float* src;
    uint32_t*    dst;
    if (row < MDIM) {
        src = x + (size_t)row * KD;
        dst = g_x32 + (size_t)row * KD;
    } else {
        const int w = (row - MDIM) >> 10;
        const int r = (row - MDIM) & 1023;
        const float* ws = (w == 0) ? qw : (w == 1) ? kw : (w == 2) ? vw : ow;
        src = ws + (size_t)r * KD;
        dst = g_w32[w] + (size_t)r * KD;
    }
    float4 f = *(const float4*)(src + j0);
    uint4 o;
    o.x = f2tf(f.x); o.y = f2tf(f.y); o.z = f2tf(f.z); o.w = f2tf(f.w);
    *(uint4*)(dst + j0) = o;
}

// ---------------------------------------------------------------------------
// TF32 tensor-core GEMM on pre-converted uint32 operands (round-3 addressing).
// C[m,n] = sum_k A[m,k]*W[n,k] + bias[n].
// outmode 0/1/2: A=g_x32, store tf32 bits into q/k/v [B,H,S,HD].
// outmode 3:     A=g_attn32, write fp32 to Cext.
// ---------------------------------------------------------------------------
#define PADK 20

__global__ void __launch_bounds__(256) gemm_tc32(const float* __restrict__ bias,
                                                 float* __restrict__ Cext,
                                                 int outmode)
{
    __shared__ uint32_t sA[2][128 * PADK];
    __shared__ uint32_t sW[2][128 * PADK];

    const int t    = threadIdx.x;
    const int lane = t & 31;
    const int warp = t >> 5;
    const int wm   = warp & 3;
    const int wn   = warp >> 2;
    const int m0   = blockIdx.y * 128;
    const int n0   = blockIdx.x * 128;

    const uint32_t* A = (outmode == 3) ? g_attn32 : g_x32;
    const uint32_t* W = g_w32[outmode];

    float c[2][8][4];
#pragma unroll
    for (int mt = 0; mt < 2; mt++)
#pragma unroll
        for (int nt = 0; nt < 8; nt++)
#pragma unroll
            for (int i = 0; i < 4; i++) c[mt][nt][i] = 0.f;

    auto issue = [&](int kt, int buf) {
        const int k0 = kt * 16;
#pragma unroll
        for (int i = 0; i < 2; i++) {
            const int idx = t + i * 256;
            const int row = idx >> 2;
            const int c4  = (idx & 3) << 2;
            cpa16(&sA[buf][row * PADK + c4], A + (size_t)(m0 + row) * KD + k0 + c4);
            cpa16(&sW[buf][row * PADK + c4], W + (size_t)(n0 + row) * KD + k0 + c4);
        }
        asm volatile("cp.async.commit_group;" ::: "memory");
    };

    issue(0, 0);
    const int NK = KD / 16;

    const int g  = lane >> 2;
    const int kq = lane & 3;

    for (int kt = 0; kt < NK; kt++) {
        asm volatile("cp.async.wait_group 0;" ::: "memory");
        __syncthreads();
        if (kt + 1 < NK) issue(kt + 1, (kt + 1) & 1);

        const uint32_t* a = &sA[kt & 1][0];
        const uint32_t* w = &sW[kt & 1][0];

#pragma unroll
        for (int ks = 0; ks < 2; ks++) {
            const int krow = ks * 8 + kq;
            uint32_t af[2][4], bf[8][2];
#pragma unroll
            for (int mt = 0; mt < 2; mt++) {
                const int rb = wm * 32 + mt * 16 + g;
                af[mt][0] = a[rb * PADK + krow];
                af[mt][1] = a[(rb + 8) * PADK + krow];
                af[mt][2] = a[rb * PADK + krow + 4];
                af[mt][3] = a[(rb + 8) * PADK + krow + 4];
            }
#pragma unroll
            for (int nt = 0; nt < 8; nt++) {
                const int nb = wn * 64 + nt * 8 + g;
                bf[nt][0] = w[nb * PADK + krow];
                bf[nt][1] = w[nb * PADK + krow + 4];
            }
#pragma unroll
            for (int mt = 0; mt < 2; mt++)
#pragma unroll
                for (int nt = 0; nt < 8; nt++)
                    mma_tf32(c[mt][nt], af[mt], bf[nt]);
        }
        __syncthreads();
    }

    if (outmode < 3) {
        uint32_t* dst = (outmode == 0) ? g_q32 : (outmode == 1) ? g_k32 : g_v32;
#pragma unroll
        for (int mt = 0; mt < 2; mt++) {
            const int r0 = m0 + wm * 32 + mt * 16 + g;
#pragma unroll
            for (int nt = 0; nt < 8; nt++) {
                const int n  = n0 + wn * 64 + nt * 8 + (kq << 1);
                const float b0 = bias[n], b1 = bias[n + 1];
                const int h  = n >> 6;
                const int hd = n & 63;
#pragma unroll
                for (int half = 0; half < 2; half++) {
                    const int r = r0 + half * 8;
                    const int b = r >> 11;
                    const int s = r & (SS - 1);
                    uint2 o;
                    o.x = f2tf(c[mt][nt][half * 2 + 0] + b0);
                    o.y = f2tf(c[mt][nt][half * 2 + 1] + b1);
                    *(uint2*)&dst[(((size_t)(b * HH + h)) * SS + s) * HD + hd] = o;
                }
            }
        }
    } else {
#pragma unroll
        for (int mt = 0; mt < 2; mt++) {
            const int r0 = m0 + wm * 32 + mt * 16 + g;
#pragma unroll
            for (int nt = 0; nt < 8; nt++) {
                const int n  = n0 + wn * 64 + nt * 8 + (kq << 1);
                const float b0 = bias[n], b1 = bias[n + 1];
#pragma unroll
                for (int half = 0; half < 2; half++) {
                    const int r = r0 + half * 8;
                    float2* p = (float2*)&Cext[(size_t)r * DD + n];
                    *p = make_float2(c[mt][nt][half * 2 + 0] + b0,
                                     c[mt][nt][half * 2 + 1] + b1);
                }
            }
        }
    }
}

// ---------------------------------------------------------------------------
// TF32 tensor-core causal flash attention (round-3 structure/addressing,
// pre-converted tf32-bit operands -> no cvt on Q/K/V fragment reads).
// Grid: (S/64 q-tiles, B*H). Block: 128 threads = 4 warps x 16 q-rows.
// ---------------------------------------------------------------------------
__device__ __forceinline__ void load_tile_sw(uint32_t* dst, const uint32_t* src, int tid) {
#pragma unroll
    for (int i = 0; i < 8; i++) {
        const int idx = tid + i * 128;     // 0..1023 uint4s
        const int rr  = idx >> 4;
        const int cc  = (idx & 15) << 2;
        uint4 f = *(const uint4*)(src + idx * 4);
        *(uint4*)(dst + rr * 64 + (cc ^ ((rr & 7) << 2))) = f;
    }
}

__global__ void __launch_bounds__(128) attn_tc32()
{
    __shared__ uint32_t Ks[64 * 64];
    __shared__ uint32_t Vs[64 * 64];

    const int bh   = blockIdx.y;
    const int qt   = (gridDim.x - 1) - blockIdx.x;  // heavy tiles first
    const int tid  = threadIdx.x;
    const int lane = tid & 31;
    const int warp = tid >> 5;
    const int g    = lane >> 2;
    const int kq   = lane & 3;

    const uint32_t* Qb = g_q32 + (size_t)bh * SS * HD;
    const uint32_t* Kb = g_k32 + (size_t)bh * SS * HD;
    const uint32_t* Vb = g_v32 + (size_t)bh * SS * HD;

    // ---- load Q tile into Ks (swizzled), extract A-fragments ----
    load_tile_sw(Ks, Qb + (size_t)qt * 64 * HD, tid);
    __syncthreads();

    uint32_t qf[8][4];
    {
        const int r0 = warp * 16 + g;
        const int r1 = r0 + 8;
        const int s0 = (r0 & 7) << 2;
        const int s1 = (r1 & 7) << 2;
#pragma unroll
        for (int ks = 0; ks < 8; ks++) {
            const int c0 = ks * 8 + kq;
            qf[ks][0] = Ks[r0 * 64 + (c0 ^ s0)];
            qf[ks][1] = Ks[r1 * 64 + (c0 ^ s1)];
            qf[ks][2] = Ks[r0 * 64 + ((c0 + 4) ^ s0)];
            qf[ks][3] = Ks[r1 * 64 + ((c0 + 4) ^ s1)];
        }
    }

    float acc[8][4];
#pragma unroll
    for (int nt = 0; nt < 8; nt++)
#pragma unroll
        for (int i = 0; i < 4; i++) acc[nt][i] = 0.f;
    float m0 = -1e30f, m1 = -1e30f, l0 = 0.f, l1 = 0.f;
    const float scale = 0.125f;   // 1/sqrt(64)

    const int row0 = warp * 16 + g;   // q-row within tile (and row0+8)

    for (int kt = 0; kt <= qt; kt++) {
        __syncthreads();
        load_tile_sw(Ks, Kb + (size_t)kt * 64 * HD, tid);
        load_tile_sw(Vs, Vb + (size_t)kt * 64 * HD, tid);
        __syncthreads();

        // ---- S = Q @ K^T ----
        float c[8][4];
#pragma unroll
        for (int nt = 0; nt < 8; nt++)
#pragma unroll
            for (int i = 0; i < 4; i++) c[nt][i] = 0.f;

#pragma unroll
        for (int ks = 0; ks < 8; ks++) {
            const int kcol = ks * 8 + kq;
#pragma unroll
            for (int nt = 0; nt < 8; nt++) {
                const int krow = nt * 8 + g;
                const int sw   = g << 2;
                uint32_t b[2];
                b[0] = Ks[krow * 64 + (kcol ^ sw)];
                b[1] = Ks[krow * 64 + ((kcol + 4) ^ sw)];
                mma_tf32(c[nt], qf[ks], b);
            }
        }

        // ---- scale + causal mask ----
        const bool diag = (kt == qt);
#pragma unroll
        for (int nt = 0; nt < 8; nt++) {
            const int colb = nt * 8 + (kq << 1);
#pragma unroll
            for (int i = 0; i < 4; i++) {
                float v = c[nt][i] * scale;
                if (diag) {
                    const int col = colb + (i & 1);
                    const int row = row0 + ((i & 2) << 2);
                    if (col > row) v = -1e30f;
                }
                c[nt][i] = v;
            }
        }

        // ---- online softmax ----
        float t0 = -1e30f, t1 = -1e30f;
#pragma unroll
        for (int nt = 0; nt < 8; nt++) {
            t0 = fmaxf(t0, fmaxf(c[nt][0], c[nt][1]));
            t1 = fmaxf(t1, fmaxf(c[nt][2], c[nt][3]));
        }
        t0 = fmaxf(t0, __shfl_xor_sync(0xffffffffu, t0, 1));
        t0 = fmaxf(t0, __shfl_xor_sync(0xffffffffu, t0, 2));
        t1 = fmaxf(t1, __shfl_xor_sync(0xffffffffu, t1, 1));
        t1 = fmaxf(t1, __shfl_xor_sync(0xffffffffu, t1, 2));

        const float mn0 = fmaxf(m0, t0);
        const float mn1 = fmaxf(m1, t1);
        const float a0  = __expf(m0 - mn0);
        const float a1  = __expf(m1 - mn1);

        float s0 = 0.f, s1 = 0.f;
#pragma unroll
        for (int nt = 0; nt < 8; nt++) {
            c[nt][0] = __expf(c[nt][0] - mn0);
            c[nt][1] = __expf(c[nt][1] - mn0);
            c[nt][2] = __expf(c[nt][2] - mn1);
            c[nt][3] = __expf(c[nt][3] - mn1);
            s0 += c[nt][0] + c[nt][1];
            s1 += c[nt][2] + c[nt][3];
        }
        s0 += __shfl_xor_sync(0xffffffffu, s0, 1);
        s0 += __shfl_xor_sync(0xffffffffu, s0, 2);
        s1 += __shfl_xor_sync(0xffffffffu, s1, 1);
        s1 += __shfl_xor_sync(0xffffffffu, s1, 2);

        l0 = l0 * a0 + s0;  m0 = mn0;
        l1 = l1 * a1 + s1;  m1 = mn1;

#pragma unroll
        for (int nt = 0; nt < 8; nt++) {
            acc[nt][0] *= a0; acc[nt][1] *= a0;
            acc[nt][2] *= a1; acc[nt][3] *= a1;
        }

        // ---- O += P @ V (P: C-layout -> A-layout via shuffles) ----
        const int src1 = (lane & ~3) | (kq >> 1);
        const int src2 = src1 + 2;
#pragma unroll
        for (int ks = 0; ks < 8; ks++) {
            const float x0 = __shfl_sync(0xffffffffu, c[ks][0], src1);
            const float x1 = __shfl_sync(0xffffffffu, c[ks][1], src1);
            const float y0 = __shfl_sync(0xffffffffu, c[ks][0], src2);
            const float y1 = __shfl_sync(0xffffffffu, c[ks][1], src2);
            const float z0 = __shfl_sync(0xffffffffu, c[ks][2], src1);
            const float z1 = __shfl_sync(0xffffffffu, c[ks][3], src1);
            const float w0 = __shfl_sync(0xffffffffu, c[ks][2], src2);
            const float w1 = __shfl_sync(0xffffffffu, c[ks][3], src2);
            uint32_t pa[4];
            pa[0] = f2tf((kq & 1) ? x1 : x0);
            pa[1] = f2tf((kq & 1) ? z1 : z0);
            pa[2] = f2tf((kq & 1) ? y1 : y0);
            pa[3] = f2tf((kq & 1) ? w1 : w0);

            const int vr0 = ks * 8 + kq;
            const int vr1 = vr0 + 4;
            const int sw0 = (vr0 & 7) << 2;
            const int sw1 = (vr1 & 7) << 2;
#pragma unroll
            for (int nt = 0; nt < 8; nt++) {
                const int vc = nt * 8 + g;
                uint32_t b[2];
                b[0] = Vs[vr0 * 64 + (vc ^ sw0)];
                b[1] = Vs[vr1 * 64 + (vc ^ sw1)];
                mma_tf32(acc[nt], pa, b);
            }
        }
    }

    // ---- finalize: normalize, store tf32 bits to g_attn32 [B,S,D] ----
    const int b = bh >> 4, h = bh & 15;
    const float inv0 = 1.f / l0;
    const float inv1 = 1.f / l1;
    const int qr0 = qt * 64 + row0;
    const int qr1 = qr0 + 8;
#pragma unroll
    for (int nt = 0; nt < 8; nt++) {
        const int col = h * HD + nt * 8 + (kq << 1);
        uint2 o0, o1;
        o0.x = f2tf(acc[nt][0] * inv0);
        o0.y = f2tf(acc[nt][1] * inv0);
        o1.x = f2tf(acc[nt][2] * inv1);
        o1.y = f2tf(acc[nt][3] * inv1);
        *(uint2*)&g_attn32[((size_t)(b * SS + qr0)) * DD + col] = o0;
        *(uint2*)&g_attn32[((size_t)(b * SS + qr1)) * DD + col] = o1;
    }
}

// ---------------------------------------------------------------------------
extern "C" void kernel_launch(void* const* d_in, const int* in_sizes, int n_in,
                              void* d_out, int out_size)
{
    const float* x  = (const float*)d_in[0];
    const float* qw = (const float*)d_in[1];
    const float* qb = (const float*)d_in[2];
    const float* kw = (const float*)d_in[3];
    const float* kb = (const float*)d_in[4];
    const float* vw = (const float*)d_in[5];
    const float* vb = (const float*)d_in[6];
    const float* ow = (const float*)d_in[7];
    const float* ob = (const float*)d_in[8];
    float* out = (float*)d_out;

    prep_tf32<<<(MDIM + 4 * DD) * (KD / 4) / 256, 256>>>(x, qw, kw, vw, ow);

    dim3 gblk(256);
    dim3 ggrd(DD / 128, MDIM / 128);   // (8, 32)

    gemm_tc32<<<ggrd, gblk>>>(qb, nullptr, 0);
    gemm_tc32<<<ggrd, gblk>>>(kb, nullptr, 1);
    gemm_tc32<<<ggrd, gblk>>>(vb, nullptr, 2);

    attn_tc32<<<dim3(SS / 64, BB * HH), 128>>>();

    gemm_tc32<<<ggrd, gblk>>>(ob, out, 3);
}

// round 6
// speedup vs baseline: 2.0990x; 1.1623x over previous
#include <cuda_runtime.h>
#include <cuda_bf16.h>
#include <cstdint>

// Problem constants: B=2, S=2048, D=1024, H=16, HD=64
#define BB   2
#define SS   2048
#define DD   1024
#define HH   16
#define HD   64
#define MDIM (BB*SS)     // 4096
#define KD   DD          // 1024

// Scratch (allocation-free rule: __device__ globals). tf32 bit patterns, PLAIN layout.
__device__ uint32_t g_x32[MDIM*KD];
__device__ uint32_t g_w32[4][DD*KD];       // qw,kw,vw,ow
__device__ uint32_t g_q32[BB*HH*SS*HD];    // [B,H,S,HD]
__device__ uint32_t g_k32[BB*HH*SS*HD];
__device__ uint32_t g_v32[BB*HH*SS*HD];
__device__ uint32_t g_attn32[BB*SS*DD];    // [B,S,D]

// ---------------------------------------------------------------------------
// helpers
// ---------------------------------------------------------------------------
__device__ __forceinline__ uint32_t f2tf(float x) {
    uint32_t r;
    asm("cvt.rna.tf32.f32 %0, %1;" : "=r"(r) : "f"(x));
    return r;
}

__device__ __forceinline__ void mma_tf32(float* c, const uint32_t* a, const uint32_t* b) {
    asm volatile(
        "mma.sync.aligned.m16n8k8.row.col.f32.tf32.tf32.f32 "
        "{%0,%1,%2,%3}, {%4,%5,%6,%7}, {%8,%9}, {%0,%1,%2,%3};"
        : "+f"(c[0]), "+f"(c[1]), "+f"(c[2]), "+f"(c[3])
        : "r"(a[0]), "r"(a[1]), "r"(a[2]), "r"(a[3]),
          "r"(b[0]), "r"(b[1]));
}

__device__ __forceinline__ void cpa16(void* smem, const void* g) {
    uint32_t s = (uint32_t)__cvta_generic_to_shared(smem);
    asm volatile("cp.async.cg.shared.global [%0], [%1], 16;" :: "r"(s), "l"(g) : "memory");
}

// ---------------------------------------------------------------------------
// prep: fp32 -> tf32 bits, PLAIN layout.
// ---------------------------------------------------------------------------
__global__ void __launch_bounds__(256) prep_tf32(const float* __restrict__ x,
                                                 const float* __restrict__ qw,
                                                 const float* __restrict__ kw,
                                                 const float* __restrict__ vw,
                                                 const float* __restrict__ ow)
{
    const int idx = blockIdx.x * 256 + threadIdx.x;
    const int row = idx >> 8;
    const int j0  = (idx & 255) << 2;

    const float* src;
    uint32_t*    dst;
    if (row < MDIM) {
        src = x + (size_t)row * KD;
        dst = g_x32 + (size_t)row * KD;
    } else {
        const int w = (row - MDIM) >> 10;
        const int r = (row - MDIM) & 1023;
        const float* ws = (w == 0) ? qw : (w == 1) ? kw : (w == 2) ? vw : ow;
        src = ws + (size_t)r * KD;
        dst = g_w32[w] + (size_t)r * KD;
    }
    float4 f = *(const float4*)(src + j0);
    uint4 o;
    o.x = f2tf(f.x); o.y = f2tf(f.y); o.z = f2tf(f.z); o.w = f2tf(f.w);
    *(uint4*)(dst + j0) = o;
}

// ---------------------------------------------------------------------------
// TF32 tensor-core GEMM, 4-stage cp.async pipeline, 1 barrier/stage.
// C[m,n] = sum_k A[m,k]*W[n,k] + bias[n].
// ---------------------------------------------------------------------------
#define PADK   20
#define STAGES 4
#define OPW    (128 * PADK)          // words per operand per stage

__global__ void __launch_bounds__(256) gemm_tc32(const float* __restrict__ bias,
                                                 float* __restrict__ Cext,
                                                 int outmode)
{
    extern __shared__ uint32_t smem[];
    uint32_t* sA = smem;                     // STAGES * OPW
    uint32_t* sW = smem + STAGES * OPW;      // STAGES * OPW

    const int t    = threadIdx.x;
    const int lane = t & 31;
    const int warp = t >> 5;
    const int wm   = warp & 3;
    const int wn   = warp >> 2;
    const int m0   = blockIdx.y * 128;
    const int n0   = blockIdx.x * 128;

    const uint32_t* A = (outmode == 3) ? g_attn32 : g_x32;
    const uint32_t* W = g_w32[outmode];

    float c[2][8][4];
#pragma unroll
    for (int mt = 0; mt < 2; mt++)
#pragma unroll
        for (int nt = 0; nt < 8; nt++)
#pragma unroll
            for (int i = 0; i < 4; i++) c[mt][nt][i] = 0.f;

    const int lrow = t >> 2;          // 0..63
    const int lc4  = (t & 3) << 2;    // 0,4,8,12

    auto issue = [&](int kt) {
        const int buf = kt & (STAGES - 1);
        const int k0  = kt * 16;
        uint32_t* da = sA + buf * OPW;
        uint32_t* dw = sW + buf * OPW;
#pragma unroll
        for (int i = 0; i < 2; i++) {
            const int row = lrow + i * 64;
            cpa16(&da[row * PADK + lc4], A + (size_t)(m0 + row) * KD + k0 + lc4);
            cpa16(&dw[row * PADK + lc4], W + (size_t)(n0 + row) * KD + k0 + lc4);
        }
        asm volatile("cp.async.commit_group;" ::: "memory");
    };

    const int NK = KD / 16;   // 64
#pragma unroll
    for (int s = 0; s < STAGES - 1; s++) issue(s);

    const int g  = lane >> 2;
    const int kq = lane & 3;

    for (int kt = 0; kt < NK; kt++) {
        asm volatile("cp.async.wait_group %0;" :: "n"(STAGES - 2) : "memory");
        __syncthreads();

        const uint32_t* a = sA + (kt & (STAGES - 1)) * OPW;
        const uint32_t* w = sW + (kt & (STAGES - 1)) * OPW;

#pragma unroll
        for (int ks = 0; ks < 2; ks++) {
            const int krow = ks * 8 + kq;
            uint32_t af[2][4], bf[8][2];
#pragma unroll
            for (int mt = 0; mt < 2; mt++) {
                const int rb = wm * 32 + mt * 16 + g;
                af[mt][0] = a[rb * PADK + krow];
                af[mt][1] = a[(rb + 8) * PADK + krow];
                af[mt][2] = a[rb * PADK + krow + 4];
                af[mt][3] = a[(rb + 8) * PADK + krow + 4];
            }
#pragma unroll
            for (int nt = 0; nt < 8; nt++) {
                const int nb = wn * 64 + nt * 8 + g;
                bf[nt][0] = w[nb * PADK + krow];
                bf[nt][1] = w[nb * PADK + krow + 4];
            }
#pragma unroll
            for (int mt = 0; mt < 2; mt++)
#pragma unroll
                for (int nt = 0; nt < 8; nt++)
                    mma_tf32(c[mt][nt], af[mt], bf[nt]);
        }

        if (kt + STAGES - 1 < NK) issue(kt + STAGES - 1);
    }

    if (outmode < 3) {
        uint32_t* dst = (outmode == 0) ? g_q32 : (outmode == 1) ? g_k32 : g_v32;
#pragma unroll
        for (int mt = 0; mt < 2; mt++) {
            const int r0 = m0 + wm * 32 + mt * 16 + g;
#pragma unroll
            for (int nt = 0; nt < 8; nt++) {
                const int n  = n0 + wn * 64 + nt * 8 + (kq << 1);
                const float b0 = bias[n], b1 = bias[n + 1];
                const int h  = n >> 6;
                const int hd = n & 63;
#pragma unroll
                for (int half = 0; half < 2; half++) {
                    const int r = r0 + half * 8;
                    const int b = r >> 11;
                    const int s = r & (SS - 1);
                    uint2 o;
                    o.x = f2tf(c[mt][nt][half * 2 + 0] + b0);
                    o.y = f2tf(c[mt][nt][half * 2 + 1] + b1);
                    *(uint2*)&dst[(((size_t)(b * HH + h)) * SS + s) * HD + hd] = o;
                }
            }
        }
    } else {
#pragma unroll
        for (int mt = 0; mt < 2; mt++) {
            const int r0 = m0 + wm * 32 + mt * 16 + g;
#pragma unroll
            for (int nt = 0; nt < 8; nt++) {
                const int n  = n0 + wn * 64 + nt * 8 + (kq << 1);
                const float b0 = bias[n], b1 = bias[n + 1];
#pragma unroll
                for (int half = 0; half < 2; half++) {
                    const int r = r0 + half * 8;
                    float2* p = (float2*)&Cext[(size_t)r * DD + n];
                    *p = make_float2(c[mt][nt][half * 2 + 0] + b0,
                                     c[mt][nt][half * 2 + 1] + b1);
                }
            }
        }
    }
}

// ---------------------------------------------------------------------------
// TF32 tensor-core causal flash attention, double-buffered cp.async K/V tiles.
// Grid: (S/64 q-tiles, B*H). Block: 128 threads = 4 warps x 16 q-rows.
// Dynamic smem: KV[2 bufs][K tile 4096 | V tile 4096] = 64KB.
// ---------------------------------------------------------------------------
__global__ void __launch_bounds__(128) attn_tc32()
{
    extern __shared__ uint32_t KV[];   // 2 * 8192 words

    const int bh   = blockIdx.y;
    const int qt   = (gridDim.x - 1) - blockIdx.x;  // heavy tiles first
    const int tid  = threadIdx.x;
    const int lane = tid & 31;
    const int warp = tid >> 5;
    const int g    = lane >> 2;
    const int kq   = lane & 3;

    const uint32_t* Qb = g_q32 + (size_t)bh * SS * HD;
    const uint32_t* Kb = g_k32 + (size_t)bh * SS * HD;
    const uint32_t* Vb = g_v32 + (size_t)bh * SS * HD;

    // ---- stage Q tile into KV[0] K-region (swizzled), extract A-fragments ----
    {
        const uint32_t* Qs = Qb + (size_t)qt * 64 * HD;
#pragma unroll
        for (int i = 0; i < 8; i++) {
            const int idx = tid + i * 128;
            const int rr  = idx >> 4;
            const int cc  = (idx & 15) << 2;
            uint4 f = *(const uint4*)(Qs + idx * 4);
            *(uint4*)(KV + rr * 64 + (cc ^ ((rr & 7) << 2))) = f;
        }
    }
    __syncthreads();

    uint32_t qf[8][4];
    {
        const int r0 = warp * 16 + g;
        const int r1 = r0 + 8;
        const int s0 = (r0 & 7) << 2;
        const int s1 = (r1 & 7) << 2;
#pragma unroll
        for (int ks = 0; ks < 8; ks++) {
            const int c0 = ks * 8 + kq;
            qf[ks][0] = KV[r0 * 64 + (c0 ^ s0)];
            qf[ks][1] = KV[r1 * 64 + (c0 ^ s1)];
            qf[ks][2] = KV[r0 * 64 + ((c0 + 4) ^ s0)];
            qf[ks][3] = KV[r1 * 64 + ((c0 + 4) ^ s1)];
        }
    }
    __syncthreads();   // Q reads done before cp.async overwrites buf0

    // tile loader: K + V of kv-tile kt into buffer buf (swizzled dst)
    auto issue_kv = [&](int kt, int buf) {
        const uint32_t* Kp = Kb + (size_t)kt * 64 * HD;
        const uint32_t* Vp = Vb + (size_t)kt * 64 * HD;
        uint32_t* kd = KV + buf * 8192;
        uint32_t* vd = kd + 4096;
#pragma unroll
        for (int i = 0; i < 8; i++) {
            const int idx = tid + i * 128;
            const int rr  = idx >> 4;
            const int cc  = (idx & 15) << 2;
            const int sa  = rr * 64 + (cc ^ ((rr & 7) << 2));
            cpa16(&kd[sa], Kp + idx * 4);
            cpa16(&vd[sa], Vp + idx * 4);
        }
        asm volatile("cp.async.commit_group;" ::: "memory");
    };

    issue_kv(0, 0);

    float acc[8][4];
#pragma unroll
    for (int nt = 0; nt < 8; nt++)
#pragma unroll
        for (int i = 0; i < 4; i++) acc[nt][i] = 0.f;
    float m0 = -1e30f, m1 = -1e30f, l0 = 0.f, l1 = 0.f;
    const float scale = 0.125f;

    const int row0 = warp * 16 + g;

    for (int kt = 0; kt <= qt; kt++) {
        asm volatile("cp.async.wait_group 0;" ::: "memory");
        __syncthreads();
        if (kt + 1 <= qt) issue_kv(kt + 1, (kt + 1) & 1);

        const uint32_t* Ks = KV + (kt & 1) * 8192;
        const uint32_t* Vs = Ks + 4096;

        // ---- S = Q @ K^T ----
        float c[8][4];
#pragma unroll
        for (int nt = 0; nt < 8; nt++)
#pragma unroll
            for (int i = 0; i < 4; i++) c[nt][i] = 0.f;

#pragma unroll
        for (int ks = 0; ks < 8; ks++) {
            const int kcol = ks * 8 + kq;
#pragma unroll
            for (int nt = 0; nt < 8; nt++) {
                const int krow = nt * 8 + g;
                const int sw   = g << 2;
                uint32_t b[2];
                b[0] = Ks[krow * 64 + (kcol ^ sw)];
                b[1] = Ks[krow * 64 + ((kcol + 4) ^ sw)];
                mma_tf32(c[nt], qf[ks], b);
            }
        }

        // ---- scale + causal mask ----
        const bool diag = (kt == qt);
#pragma unroll
        for (int nt = 0; nt < 8; nt++) {
            const int colb = nt * 8 + (kq << 1);
#pragma unroll
            for (int i = 0; i < 4; i++) {
                float v = c[nt][i] * scale;
                if (diag) {
                    const int col = colb + (i & 1);
                    const int row = row0 + ((i & 2) << 2);
                    if (col > row) v = -1e30f;
                }
                c[nt][i] = v;
            }
        }

        // ---- online softmax ----
        float t0 = -1e30f, t1 = -1e30f;
#pragma unroll
        for (int nt = 0; nt < 8; nt++) {
            t0 = fmaxf(t0, fmaxf(c[nt][0], c[nt][1]));
            t1 = fmaxf(t1, fmaxf(c[nt][2], c[nt][3]));
        }
        t0 = fmaxf(t0, __shfl_xor_sync(0xffffffffu, t0, 1));
        t0 = fmaxf(t0, __shfl_xor_sync(0xffffffffu, t0, 2));
        t1 = fmaxf(t1, __shfl_xor_sync(0xffffffffu, t1, 1));
        t1 = fmaxf(t1, __shfl_xor_sync(0xffffffffu, t1, 2));

        const float mn0 = fmaxf(m0, t0);
        const float mn1 = fmaxf(m1, t1);
        const float a0  = __expf(m0 - mn0);
        const float a1  = __expf(m1 - mn1);

        float s0 = 0.f, s1 = 0.f;
#pragma unroll
        for (int nt = 0; nt < 8; nt++) {
            c[nt][0] = __expf(c[nt][0] - mn0);
            c[nt][1] = __expf(c[nt][1] - mn0);
            c[nt][2] = __expf(c[nt][2] - mn1);
            c[nt][3] = __expf(c[nt][3] - mn1);
            s0 += c[nt][0] + c[nt][1];
            s1 += c[nt][2] + c[nt][3];
        }
        s0 += __shfl_xor_sync(0xffffffffu, s0, 1);
        s0 += __shfl_xor_sync(0xffffffffu, s0, 2);
        s1 += __shfl_xor_sync(0xffffffffu, s1, 1);
        s1 += __shfl_xor_sync(0xffffffffu, s1, 2);

        l0 = l0 * a0 + s0;  m0 = mn0;
        l1 = l1 * a1 + s1;  m1 = mn1;

#pragma unroll
        for (int nt = 0; nt < 8; nt++) {
            acc[nt][0] *= a0; acc[nt][1] *= a0;
            acc[nt][2] *= a1; acc[nt][3] *= a1;
        }

        // ---- O += P @ V (P: C-layout -> A-layout via shuffles) ----
        const int src1 = (lane & ~3) | (kq >> 1);
        const int src2 = src1 + 2;
#pragma unroll
        for (int ks = 0; ks < 8; ks++) {
            const float x0 = __shfl_sync(0xffffffffu, c[ks][0], src1);
            const float x1 = __shfl_sync(0xffffffffu, c[ks][1], src1);
            const float y0 = __shfl_sync(0xffffffffu, c[ks][0], src2);
            const float y1 = __shfl_sync(0xffffffffu, c[ks][1], src2);
            const float z0 = __shfl_sync(0xffffffffu, c[ks][2], src1);
            const float z1 = __shfl_sync(0xffffffffu, c[ks][3], src1);
            const float w0 = __shfl_sync(0xffffffffu, c[ks][2], src2);
            const float w1 = __shfl_sync(0xffffffffu, c[ks][3], src2);
            uint32_t pa[4];
            pa[0] = f2tf((kq & 1) ? x1 : x0);
            pa[1] = f2tf((kq & 1) ? z1 : z0);
            pa[2] = f2tf((kq & 1) ? y1 : y0);
            pa[3] = f2tf((kq & 1) ? w1 : w0);

            const int vr0 = ks * 8 + kq;
            const int vr1 = vr0 + 4;
            const int sw0 = (vr0 & 7) << 2;
            const int sw1 = (vr1 & 7) << 2;
#pragma unroll
            for (int nt = 0; nt < 8; nt++) {
                const int vc = nt * 8 + g;
                uint32_t b[2];
                b[0] = Vs[vr0 * 64 + (vc ^ sw0)];
                b[1] = Vs[vr1 * 64 + (vc ^ sw1)];
                mma_tf32(acc[nt], pa, b);
            }
        }
    }

    // ---- finalize ----
    const int b = bh >> 4, h = bh & 15;
    const float inv0 = 1.f / l0;
    const float inv1 = 1.f / l1;
    const int qr0 = qt * 64 + row0;
    const int qr1 = qr0 + 8;
#pragma unroll
    for (int nt = 0; nt < 8; nt++) {
        const int col = h * HD + nt * 8 + (kq << 1);
        uint2 o0, o1;
        o0.x = f2tf(acc[nt][0] * inv0);
        o0.y = f2tf(acc[nt][1] * inv0);
        o1.x = f2tf(acc[nt][2] * inv1);
        o1.y = f2tf(acc[nt][3] * inv1);
        *(uint2*)&g_attn32[((size_t)(b * SS + qr0)) * DD + col] = o0;
        *(uint2*)&g_attn32[((size_t)(b * SS + qr1)) * DD + col] = o1;
    }
}

// ---------------------------------------------------------------------------
extern "C" void kernel_launch(void* const* d_in, const int* in_sizes, int n_in,
                              void* d_out, int out_size)
{
    const float* x  = (const float*)d_in[0];
    const float* qw = (const float*)d_in[1];
    const float* qb = (const float*)d_in[2];
    const float* kw = (const float*)d_in[3];
    const float* kb = (const float*)d_in[4];
    const float* vw = (const float*)d_in[5];
    const float* vb = (const float*)d_in[6];
    const float* ow = (const float*)d_in[7];
    const float* ob = (const float*)d_in[8];
    float* out = (float*)d_out;

    const int gemm_smem = STAGES * OPW * 2 * (int)sizeof(uint32_t);  // 80 KB
    const int attn_smem = 2 * 8192 * (int)sizeof(uint32_t);          // 64 KB
    cudaFuncSetAttribute(gemm_tc32, cudaFuncAttributeMaxDynamicSharedMemorySize, gemm_smem);
    cudaFuncSetAttribute(attn_tc32, cudaFuncAttributeMaxDynamicSharedMemorySize, attn_smem);

    prep_tf32<<<(MDIM + 4 * DD) * (KD / 4) / 256, 256>>>(x, qw, kw, vw, ow);

    dim3 gblk(256);
    dim3 ggrd(DD / 128, MDIM / 128);   // (8, 32)

    gemm_tc32<<<ggrd, gblk, gemm_smem>>>(qb, nullptr, 0);
    gemm_tc32<<<ggrd, gblk, gemm_smem>>>(kb, nullptr, 1);
    gemm_tc32<<<ggrd, gblk, gemm_smem>>>(vb, nullptr, 2);

    attn_tc32<<<dim3(SS / 64, BB * HH), 128, attn_smem>>>();

    gemm_tc32<<<ggrd, gblk, gemm_smem>>>(ob, out, 3);
}

// round 7
// speedup vs baseline: 2.2040x; 1.0500x over previous
#include <cuda_runtime.h>
#include <cuda_bf16.h>
#include <cstdint>

// Problem constants: B=2, S=2048, D=1024, H=16, HD=64
#define BB   2
#define SS   2048
#define DD   1024
#define HH   16
#define HD   64
#define MDIM (BB*SS)     // 4096
#define KD   DD          // 1024

// Scratch (allocation-free rule). tf32 bit patterns.
// g_x32 / g_w32 / g_attn32: k-dim PAIR-PERMUTED (storage[permf(k)] = val(k)).
// g_q32/g_k32/g_v32: plain layout (consumed by attention).
__device__ uint32_t g_x32[MDIM*KD];
__device__ uint32_t g_w32[4][DD*KD];       // qw,kw,vw,ow
__device__ uint32_t g_q32[BB*HH*SS*HD];    // [B,H,S,HD]
__device__ uint32_t g_k32[BB*HH*SS*HD];
__device__ uint32_t g_v32[BB*HH*SS*HD];
__device__ uint32_t g_attn32[BB*SS*DD];    // [B,S,D], D pair-permuted

// permf(k): storage slot of logical k. Pairs (k, k+4) -> (2j, 2j+1) adjacent.
// permi = inverse: storage[j] holds logical permi(j).
__device__ __forceinline__ int permi(int j) { return (j & ~7) | ((j >> 1) & 3) | ((j & 1) << 2); }

__device__ __forceinline__ uint32_t f2tf(float x) {
    uint32_t r;
    asm("cvt.rna.tf32.f32 %0, %1;" : "=r"(r) : "f"(x));
    return r;
}

__device__ __forceinline__ void mma_tf32(float* c, const uint32_t* a, const uint32_t* b) {
    asm volatile(
        "mma.sync.aligned.m16n8k8.row.col.f32.tf32.tf32.f32 "
        "{%0,%1,%2,%3}, {%4,%5,%6,%7}, {%8,%9}, {%0,%1,%2,%3};"
        : "+f"(c[0]), "+f"(c[1]), "+f"(c[2]), "+f"(c[3])
        : "r"(a[0]), "r"(a[1]), "r"(a[2]), "r"(a[3]),
          "r"(b[0]), "r"(b[1]));
}

__device__ __forceinline__ void cpa16(void* smem, const void* g) {
    uint32_t s = (uint32_t)__cvta_generic_to_shared(smem);
    asm volatile("cp.async.cg.shared.global [%0], [%1], 16;" :: "r"(s), "l"(g) : "memory");
}

// ---------------------------------------------------------------------------
// prep: fp32 -> tf32 bits, k-dim pair-permuted (gather via permi).
// ---------------------------------------------------------------------------
__global__ void __launch_bounds__(256) prep_tf32(const float* __restrict__ x,
                                                 const float* __restrict__ qw,
                                                 const float* __restrict__ kw,
                                                 const float* __restrict__ vw,
                                                 const float* __restrict__ ow)
{
    const int idx = blockIdx.x * 256 + threadIdx.x;
    const int row = idx >> 8;
    const int j0  = (idx & 255) << 2;

    const float* src;
    uint32_t*    dst;
    if (row < MDIM) {
        src = x + (size_t)row * KD;
        dst = g_x32 + (size_t)row * KD;
    } else {
        const int w = (row - MDIM) >> 10;
        const int r = (row - MDIM) & 1023;
        const float* ws = (w == 0) ? qw : (w == 1) ? kw : (w == 2) ? vw : ow;
        src = ws + (size_t)r * KD;
        dst = g_w32[w] + (size_t)r * KD;
    }
    uint4 o;
    o.x = f2tf(src[permi(j0 + 0)]);
    o.y = f2tf(src[permi(j0 + 1)]);
    o.z = f2tf(src[permi(j0 + 2)]);
    o.w = f2tf(src[permi(j0 + 3)]);
    *(uint4*)(dst + j0) = o;
}

// ---------------------------------------------------------------------------
// TF32 tensor-core GEMM: BK=32 per stage, 2-stage cp.async, LDS.64 fragments.
// pitch 40 words/row: frag bank-pair (20g+kq)%16 distinct per half-warp;
// store banks (8r+4c)%32 distinct per quarter-warp.
// mode >= 0: that outmode; mode < 0: outmode = blockIdx.z (fused QKV).
// ---------------------------------------------------------------------------
#define PITCH  40
#define OPW    (128 * PITCH)          // words per operand per stage

__global__ void __launch_bounds__(256) gemm_tc32(const float* __restrict__ bias_q,
                                                 const float* __restrict__ bias_k,
                                                 const float* __restrict__ bias_v,
                                                 float* __restrict__ Cext,
                                                 int mode)
{
    extern __shared__ uint32_t smem[];
    uint32_t* sA = smem;               // 2 * OPW
    uint32_t* sW = smem + 2 * OPW;     // 2 * OPW

    const int outmode = (mode >= 0) ? mode : (int)blockIdx.z;
    const float* bias = (outmode == 0) ? bias_q : (outmode == 1) ? bias_k
                       : (outmode == 2) ? bias_v : bias_q;

    const int t    = threadIdx.x;
    const int lane = t & 31;
    const int warp = t >> 5;
    const int wm   = warp & 3;
    const int wn   = warp >> 2;
    const int m0   = blockIdx.y * 128;
    const int n0   = blockIdx.x * 128;

    const uint32_t* A = (outmode == 3) ? g_attn32 : g_x32;
    const uint32_t* W = g_w32[outmode];

    float c[2][8][4];
#pragma unroll
    for (int mt = 0; mt < 2; mt++)
#pragma unroll
        for (int nt = 0; nt < 8; nt++)
#pragma unroll
            for (int i = 0; i < 4; i++) c[mt][nt][i] = 0.f;

    // stage loader: 128 rows x 32 words per operand = 1024 uint4; 4/thread/operand
    const int lrow = t >> 3;           // 0..31
    const int lc4  = (t & 7) << 2;     // 0,4,...,28

    auto issue = [&](int kt) {
        const int buf = kt & 1;
        const int k0  = kt * 32;
        uint32_t* da = sA + buf * OPW;
        uint32_t* dw = sW + buf * OPW;
#pragma unroll
        for (int i = 0; i < 4; i++) {
            const int row = lrow + i * 32;
            cpa16(&da[row * PITCH + lc4], A + (size_t)(m0 + row) * KD + k0 + lc4);
            cpa16(&dw[row * PITCH + lc4], W + (size_t)(n0 + row) * KD + k0 + lc4);
        }
        asm volatile("cp.async.commit_group;" ::: "memory");
    };

    const int NK = KD / 32;   // 32 stages
    issue(0);

    const int g  = lane >> 2;
    const int kq = lane & 3;

    for (int kt = 0; kt < NK; kt++) {
        asm volatile("cp.async.wait_group 0;" ::: "memory");
        __syncthreads();
        if (kt + 1 < NK) issue(kt + 1);

        const uint32_t* a = sA + (kt & 1) * OPW;
        const uint32_t* w = sW + (kt & 1) * OPW;

#pragma unroll
        for (int ks = 0; ks < 4; ks++) {
            const int kk = ks * 8 + (kq << 1);   // permuted (k, k+4) pair
            uint32_t af[2][4], bf[8][2];
#pragma unroll
            for (int mt = 0; mt < 2; mt++) {
                const int rb = wm * 32 + mt * 16 + g;
                uint2 v0 = *(const uint2*)&a[rb * PITCH + kk];
                uint2 v1 = *(const uint2*)&a[(rb + 8) * PITCH + kk];
                af[mt][0] = v0.x; af[mt][1] = v1.x; af[mt][2] = v0.y; af[mt][3] = v1.y;
            }
#pragma unroll
            for (int nt = 0; nt < 8; nt++) {
                const int nb = wn * 64 + nt * 8 + g;
                uint2 v = *(const uint2*)&w[nb * PITCH + kk];
                bf[nt][0] = v.x; bf[nt][1] = v.y;
            }
#pragma unroll
            for (int mt = 0; mt < 2; mt++)
#pragma unroll
                for (int nt = 0; nt < 8; nt++)
                    mma_tf32(c[mt][nt], af[mt], bf[nt]);
        }
    }

    if (outmode < 3) {
        uint32_t* dst = (outmode == 0) ? g_q32 : (outmode == 1) ? g_k32 : g_v32;
#pragma unroll
        for (int mt = 0; mt < 2; mt++) {
            const int r0 = m0 + wm * 32 + mt * 16 + g;
#pragma unroll
            for (int nt = 0; nt < 8; nt++) {
                const int n  = n0 + wn * 64 + nt * 8 + (kq << 1);
                const float b0 = bias[n], b1 = bias[n + 1];
                const int h  = n >> 6;
                const int hd = n & 63;
#pragma unroll
                for (int half = 0; half < 2; half++) {
                    const int r = r0 + half * 8;
                    const int b = r >> 11;
                    const int s = r & (SS - 1);
                    uint2 o;
                    o.x = f2tf(c[mt][nt][half * 2 + 0] + b0);
                    o.y = f2tf(c[mt][nt][half * 2 + 1] + b1);
                    *(uint2*)&dst[(((size_t)(b * HH + h)) * SS + s) * HD + hd] = o;
                }
            }
        }
    } else {
#pragma unroll
        for (int mt = 0; mt < 2; mt++) {
            const int r0 = m0 + wm * 32 + mt * 16 + g;
#pragma unroll
            for (int nt = 0; nt < 8; nt++) {
                const int n  = n0 + wn * 64 + nt * 8 + (kq << 1);
                const float b0 = bias[n], b1 = bias[n + 1];
#pragma unroll
                for (int half = 0; half < 2; half++) {
                    const int r = r0 + half * 8;
                    float2* p = (float2*)&Cext[(size_t)r * DD + n];
                    *p = make_float2(c[mt][nt][half * 2 + 0] + b0,
                                     c[mt][nt][half * 2 + 1] + b1);
                }
            }
        }
    }
}

// ---------------------------------------------------------------------------
// TF32 tensor-core causal flash attention (unchanged structure from round 6),
// EXCEPT the final store into g_attn32 uses the D pair-permutation.
// ---------------------------------------------------------------------------
__global__ void __launch_bounds__(128) attn_tc32()
{
    extern __shared__ uint32_t KV[];   // 2 * 8192 words

    const int bh   = blockIdx.y;
    const int qt   = (gridDim.x - 1) - blockIdx.x;
    const int tid  = threadIdx.x;
    const int lane = tid & 31;
    const int warp = tid >> 5;
    const int g    = lane >> 2;
    const int kq   = lane & 3;

    const uint32_t* Qb = g_q32 + (size_t)bh * SS * HD;
    const uint32_t* Kb = g_k32 + (size_t)bh * SS * HD;
    const uint32_t* Vb = g_v32 + (size_t)bh * SS * HD;

    {
        const uint32_t* Qs = Qb + (size_t)qt * 64 * HD;
#pragma unroll
        for (int i = 0; i < 8; i++) {
            const int idx = tid + i * 128;
            const int rr  = idx >> 4;
            const int cc  = (idx & 15) << 2;
            uint4 f = *(const uint4*)(Qs + idx * 4);
            *(uint4*)(KV + rr * 64 + (cc ^ ((rr & 7) << 2))) = f;
        }
    }
    __syncthreads();

    uint32_t qf[8][4];
    {
        const int r0 = warp * 16 + g;
        const int r1 = r0 + 8;
        const int s0 = (r0 & 7) << 2;
        const int s1 = (r1 & 7) << 2;
#pragma unroll
        for (int ks = 0; ks < 8; ks++) {
            const int c0 = ks * 8 + kq;
            qf[ks][0] = KV[r0 * 64 + (c0 ^ s0)];
            qf[ks][1] = KV[r1 * 64 + (c0 ^ s1)];
            qf[ks][2] = KV[r0 * 64 + ((c0 + 4) ^ s0)];
            qf[ks][3] = KV[r1 * 64 + ((c0 + 4) ^ s1)];
        }
    }
    __syncthreads();

    auto issue_kv = [&](int kt, int buf) {
        const uint32_t* Kp = Kb + (size_t)kt * 64 * HD;
        const uint32_t* Vp = Vb + (size_t)kt * 64 * HD;
        uint32_t* kd = KV + buf * 8192;
        uint32_t* vd = kd + 4096;
#pragma unroll
        for (int i = 0; i < 8; i++) {
            const int idx = tid + i * 128;
            const int rr  = idx >> 4;
            const int cc  = (idx & 15) << 2;
            const int sa  = rr * 64 + (cc ^ ((rr & 7) << 2));
            cpa16(&kd[sa], Kp + idx * 4);
            cpa16(&vd[sa], Vp + idx * 4);
        }
        asm volatile("cp.async.commit_group;" ::: "memory");
    };

    issue_kv(0, 0);

    float acc[8][4];
#pragma unroll
    for (int nt = 0; nt < 8; nt++)
#pragma unroll
        for (int i = 0; i < 4; i++) acc[nt][i] = 0.f;
    float m0 = -1e30f, m1 = -1e30f, l0 = 0.f, l1 = 0.f;
    const float scale = 0.125f;

    const int row0 = warp * 16 + g;

    for (int kt = 0; kt <= qt; kt++) {
        asm volatile("cp.async.wait_group 0;" ::: "memory");
        __syncthreads();
        if (kt + 1 <= qt) issue_kv(kt + 1, (kt + 1) & 1);

        const uint32_t* Ks = KV + (kt & 1) * 8192;
        const uint32_t* Vs = Ks + 4096;

        float c[8][4];
#pragma unroll
        for (int nt = 0; nt < 8; nt++)
#pragma unroll
            for (int i = 0; i < 4; i++) c[nt][i] = 0.f;

#pragma unroll
        for (int ks = 0; ks < 8; ks++) {
            const int kcol = ks * 8 + kq;
#pragma unroll
            for (int nt = 0; nt < 8; nt++) {
                const int krow = nt * 8 + g;
                const int sw   = g << 2;
                uint32_t b[2];
                b[0] = Ks[krow * 64 + (kcol ^ sw)];
                b[1] = Ks[krow * 64 + ((kcol + 4) ^ sw)];
                mma_tf32(c[nt], qf[ks], b);
            }
        }

        const bool diag = (kt == qt);
#pragma unroll
        for (int nt = 0; nt < 8; nt++) {
            const int colb = nt * 8 + (kq << 1);
#pragma unroll
            for (int i = 0; i < 4; i++) {
                float v = c[nt][i] * scale;
                if (diag) {
                    const int col = colb + (i & 1);
                    const int row = row0 + ((i & 2) << 2);
                    if (col > row) v = -1e30f;
                }
                c[nt][i] = v;
            }
        }

        float t0 = -1e30f, t1 = -1e30f;
#pragma unroll
        for (int nt = 0; nt < 8; nt++) {
            t0 = fmaxf(t0, fmaxf(c[nt][0], c[nt][1]));
            t1 = fmaxf(t1, fmaxf(c[nt][2], c[nt][3]));
        }
        t0 = fmaxf(t0, __shfl_xor_sync(0xffffffffu, t0, 1));
        t0 = fmaxf(t0, __shfl_xor_sync(0xffffffffu, t0, 2));
        t1 = fmaxf(t1, __shfl_xor_sync(0xffffffffu, t1, 1));
        t1 = fmaxf(t1, __shfl_xor_sync(0xffffffffu, t1, 2));

        const float mn0 = fmaxf(m0, t0);
        const float mn1 = fmaxf(m1, t1);
        const float a0  = __expf(m0 - mn0);
        const float a1  = __expf(m1 - mn1);

        float s0 = 0.f, s1 = 0.f;
#pragma unroll
        for (int nt = 0; nt < 8; nt++) {
            c[nt][0] = __expf(c[nt][0] - mn0);
            c[nt][1] = __expf(c[nt][1] - mn0);
            c[nt][2] = __expf(c[nt][2] - mn1);
            c[nt][3] = __expf(c[nt][3] - mn1);
            s0 += c[nt][0] + c[nt][1];
            s1 += c[nt][2] + c[nt][3];
        }
        s0 += __shfl_xor_sync(0xffffffffu, s0, 1);
        s0 += __shfl_xor_sync(0xffffffffu, s0, 2);
        s1 += __shfl_xor_sync(0xffffffffu, s1, 1);
        s1 += __shfl_xor_sync(0xffffffffu, s1, 2);

        l0 = l0 * a0 + s0;  m0 = mn0;
        l1 = l1 * a1 + s1;  m1 = mn1;

#pragma unroll
        for (int nt = 0; nt < 8; nt++) {
            acc[nt][0] *= a0; acc[nt][1] *= a0;
            acc[nt][2] *= a1; acc[nt][3] *= a1;
        }

        const int src1 = (lane & ~3) | (kq >> 1);
        const int src2 = src1 + 2;
#pragma unroll
        for (int ks = 0; ks < 8; ks++) {
            const float x0 = __shfl_sync(0xffffffffu, c[ks][0], src1);
            const float x1 = __shfl_sync(0xffffffffu, c[ks][1], src1);
            const float y0 = __shfl_sync(0xffffffffu, c[ks][0], src2);
            const float y1 = __shfl_sync(0xffffffffu, c[ks][1], src2);
            const float z0 = __shfl_sync(0xffffffffu, c[ks][2], src1);
            const float z1 = __shfl_sync(0xffffffffu, c[ks][3], src1);
            const float w0 = __shfl_sync(0xffffffffu, c[ks][2], src2);
            const float w1 = __shfl_sync(0xffffffffu, c[ks][3], src2);
            uint32_t pa[4];
            pa[0] = f2tf((kq & 1) ? x1 : x0);
            pa[1] = f2tf((kq & 1) ? z1 : z0);
            pa[2] = f2tf((kq & 1) ? y1 : y0);
            pa[3] = f2tf((kq & 1) ? w1 : w0);

            const int vr0 = ks * 8 + kq;
            const int vr1 = vr0 + 4;
            const int sw0 = (vr0 & 7) << 2;
            const int sw1 = (vr1 & 7) << 2;
#pragma unroll
            for (int nt = 0; nt < 8; nt++) {
                const int vc = nt * 8 + g;
                uint32_t b[2];
                b[0] = Vs[vr0 * 64 + (vc ^ sw0)];
                b[1] = Vs[vr1 * 64 + (vc ^ sw1)];
                mma_tf32(acc[nt], pa, b);
            }
        }
    }

    // ---- finalize: store tf32 bits, D pair-permuted ----
    // logical cols (n, n+1), n = base + 2kq -> storage (base+pf, base+pf+2),
    // pf = ((kq&1)<<2) | (kq>>1)   [0,4,1,5 for kq=0..3]
    const int b = bh >> 4, h = bh & 15;
    const float inv0 = 1.f / l0;
    const float inv1 = 1.f / l1;
    const int qr0 = qt * 64 + row0;
    const int qr1 = qr0 + 8;
    const int pf  = ((kq & 1) << 2) | (kq >> 1);
#pragma unroll
    for (int nt = 0; nt < 8; nt++) {
        const int base = h * HD + nt * 8;
        uint32_t* p0 = &g_attn32[((size_t)(b * SS + qr0)) * DD + base];
        uint32_t* p1 = &g_attn32[((size_t)(b * SS + qr1)) * DD + base];
        p0[pf]     = f2tf(acc[nt][0] * inv0);
        p0[pf + 2] = f2tf(acc[nt][1] * inv0);
        p1[pf]     = f2tf(acc[nt][2] * inv1);
        p1[pf + 2] = f2tf(acc[nt][3] * inv1);
    }
}

// ---------------------------------------------------------------------------
extern "C" void kernel_launch(void* const* d_in, const int* in_sizes, int n_in,
                              void* d_out, int out_size)
{
    const float* x  = (const float*)d_in[0];
    const float* qw = (const float*)d_in[1];
    const float* qb = (const float*)d_in[2];
    const float* kw = (const float*)d_in[3];
    const float* kb = (const float*)d_in[4];
    const float* vw = (const float*)d_in[5];
    const float* vb = (const float*)d_in[6];
    const float* ow = (const float*)d_in[7];
    const float* ob = (const float*)d_in[8];
    float* out = (float*)d_out;

    const int gemm_smem = 4 * OPW * (int)sizeof(uint32_t);   // 80 KB
    const int attn_smem = 2 * 8192 * (int)sizeof(uint32_t);  // 64 KB
    cudaFuncSetAttribute(gemm_tc32, cudaFuncAttributeMaxDynamicSharedMemorySize, gemm_smem);
    cudaFuncSetAttribute(attn_tc32, cudaFuncAttributeMaxDynamicSharedMemorySize, attn_smem);

    prep_tf32<<<(MDIM + 4 * DD) * (KD / 4) / 256, 256>>>(x, qw, kw, vw, ow);

    dim3 gblk(256);

    // fused QKV: z selects outmode
    gemm_tc32<<<dim3(DD / 128, MDIM / 128, 3), gblk, gemm_smem>>>(qb, kb, vb, nullptr, -1);

    attn_tc32<<<dim3(SS / 64, BB * HH), 128, attn_smem>>>();

    gemm_tc32<<<dim3(DD / 128, MDIM / 128, 1), gblk, gemm_smem>>>(ob, ob, ob, out, 3);
}

// round 9
// speedup vs baseline: 4.4609x; 2.0240x over previous
#include <cuda_runtime.h>
#include <cuda_fp16.h>
#include <cstdint>

// Problem constants: B=2, S=2048, D=1024, H=16, HD=64
#define BB   2
#define SS   2048
#define DD   1024
#define HH   16
#define HD   64
#define MDIM (BB*SS)     // 4096
#define KD   DD          // 1024
#define KW   (KD/2)      // 512 fp16x2 words per row
#define HDW  (HD/2)      // 32 words per head row

// Scratch (allocation-free rule). fp16x2 packed words, plain layouts.
__device__ uint32_t g_x16[MDIM*KW];
__device__ uint32_t g_w16[4][DD*KW];          // qw,kw,vw,ow
__device__ uint32_t g_q16[BB*HH*SS*HDW];      // [B,H,S,HD] (q pre-scaled by 1/8)
__device__ uint32_t g_k16[BB*HH*SS*HDW];
__device__ uint32_t g_v16[BB*HH*SS*HDW];
__device__ uint32_t g_attn16[BB*SS*DD/2];     // [B,S,D]

// ---------------------------------------------------------------------------
// helpers
// ---------------------------------------------------------------------------
__device__ __forceinline__ uint32_t packh2(float lo, float hi) {
    uint32_t r;
    asm("cvt.rn.f16x2.f32 %0, %1, %2;" : "=r"(r) : "f"(hi), "f"(lo));
    return r;   // low half = lo
}

__device__ __forceinline__ void mma_f16(float* c, const uint32_t* a, const uint32_t* b) {
    asm volatile(
        "mma.sync.aligned.m16n8k16.row.col.f32.f16.f16.f32 "
        "{%0,%1,%2,%3}, {%4,%5,%6,%7}, {%8,%9}, {%0,%1,%2,%3};"
        : "+f"(c[0]), "+f"(c[1]), "+f"(c[2]), "+f"(c[3])
        : "r"(a[0]), "r"(a[1]), "r"(a[2]), "r"(a[3]),
          "r"(b[0]), "r"(b[1]));
}

__device__ __forceinline__ void ldsm4(uint32_t addr, uint32_t& r0, uint32_t& r1,
                                      uint32_t& r2, uint32_t& r3) {
    asm volatile("ldmatrix.sync.aligned.m8n8.x4.shared.b16 {%0,%1,%2,%3}, [%4];"
                 : "=r"(r0), "=r"(r1), "=r"(r2), "=r"(r3) : "r"(addr));
}
__device__ __forceinline__ void ldsm4t(uint32_t addr, uint32_t& r0, uint32_t& r1,
                                       uint32_t& r2, uint32_t& r3) {
    asm volatile("ldmatrix.sync.aligned.m8n8.x4.trans.shared.b16 {%0,%1,%2,%3}, [%4];"
                 : "=r"(r0), "=r"(r1), "=r"(r2), "=r"(r3) : "r"(addr));
}

__device__ __forceinline__ void cpa16s(uint32_t saddr, const void* g) {
    asm volatile("cp.async.cg.shared.global [%0], [%1], 16;" :: "r"(saddr), "l"(g) : "memory");
}

__device__ __forceinline__ uint32_t smem_u32(const void* p) {
    uint32_t a;
    asm("{ .reg .u64 t; cvta.to.shared.u64 t, %1; cvt.u32.u64 %0, t; }" : "=r"(a) : "l"(p));
    return a;
}

// swizzled byte address of 16B chunk (row: 128B pitch, chunk 0..7)
__device__ __forceinline__ uint32_t sw_addr(uint32_t base, int row, int chunk) {
    return base + (uint32_t)(row * 128 + ((chunk ^ (row & 7)) << 4));
}

// ---------------------------------------------------------------------------
// prep: fp32 -> fp16x2 words. 8192 rows x 512 words (x then qw,kw,vw,ow).
// ---------------------------------------------------------------------------
__global__ void __launch_bounds__(256) prep_f16(const float* __restrict__ x,
                                                const float* __restrict__ qw,
                                                const float* __restrict__ kw,
                                                const float* __restrict__ vw,
                                                const float* __restrict__ ow)
{
    const int idx = blockIdx.x * 256 + threadIdx.x;  // word-quad id (4 words = 8 floats)
    const int row = idx >> 7;                        // 128 quads per 1024-float row
    const int q8  = (idx & 127) << 3;                // float offset

    const float* src;
    uint32_t*    dst;
    if (row < MDIM) {
        src = x + (size_t)row * KD;
        dst = g_x16 + (size_t)row * KW;
    } else {
        const int w = (row - MDIM) >> 10;
        const int r = (row - MDIM) & 1023;
        const float* ws = (w == 0) ? qw : (w == 1) ? kw : (w == 2) ? vw : ow;
        src = ws + (size_t)r * KD;
        dst = g_w16[w] + (size_t)r * KW;
    }
    float4 f0 = *(const float4*)(src + q8);
    float4 f1 = *(const float4*)(src + q8 + 4);
    uint4 o;
    o.x = packh2(f0.x, f0.y); o.y = packh2(f0.z, f0.w);
    o.z = packh2(f1.x, f1.y); o.w = packh2(f1.z, f1.w);
    *(uint4*)(dst + (q8 >> 1)) = o;
}

// ---------------------------------------------------------------------------
// FP16 tensor-core GEMM: C[m,n] = sum_k A[m,k]*W[n,k] + bias[n].
// 128x128 tile, 256 thr (8 warps: 4m x 2n, warp tile 32x64).
// BK=64 halves/stage (128B rows, XOR-swizzled), 3-stage cp.async.
// outmode 0/1/2: store fp16 into q/k/v [B,H,S,HD] (q scaled by 1/8).
// outmode 3: A=g_attn16, fp32 out + bias.
// ---------------------------------------------------------------------------
#define GSTG  3
#define TILEW 4096    // words per operand per stage (128 rows * 32 words)

__global__ void __launch_bounds__(256) gemm_f16(const float* __restrict__ bias_q,
                                                const float* __restrict__ bias_k,
                                                const float* __restrict__ bias_v,
                                                float* __restrict__ Cext,
                                                int mode)
{
    extern __shared__ uint32_t sm[];
    const uint32_t smb = smem_u32(sm);

    const int outmode = (mode >= 0) ? mode : (int)blockIdx.z;
    const float* bias = (outmode == 0) ? bias_q : (outmode == 1) ? bias_k
                       : (outmode == 2) ? bias_v : bias_q;

    const int t    = threadIdx.x;
    const int lane = t & 31;
    const int warp = t >> 5;
    const int wm   = warp & 3;
    const int wn   = warp >> 2;
    const int m0   = blockIdx.y * 128;
    const int n0   = blockIdx.x * 128;

    const uint32_t* A = (outmode == 3) ? g_attn16 : g_x16;
    const uint32_t* W = g_w16[outmode];

    float c[2][8][4];
#pragma unroll
    for (int mt = 0; mt < 2; mt++)
#pragma unroll
        for (int nt = 0; nt < 8; nt++)
#pragma unroll
            for (int i = 0; i < 4; i++) c[mt][nt][i] = 0.f;

    auto issue = [&](int s) {
        const int bufw = (s % GSTG) * 2 * TILEW;
#pragma unroll
        for (int i = 0; i < 4; i++) {
            const int idx = t + i * 256;          // 0..1023 chunks
            const int row = idx >> 3;
            const int c4  = idx & 7;
            const uint32_t sd = (uint32_t)(row * 128 + ((c4 ^ (row & 7)) << 4));
            cpa16s(smb + bufw * 4 + sd,             A + (size_t)(m0 + row) * KW + s * 32 + c4 * 4);
            cpa16s(smb + (bufw + TILEW) * 4 + sd,   W + (size_t)(n0 + row) * KW + s * 32 + c4 * 4);
        }
        asm volatile("cp.async.commit_group;" ::: "memory");
    };

    const int NK = KD / 64;   // 16 stages
    issue(0); issue(1);

    for (int s = 0; s < NK; s++) {
        if (s == NK - 1) asm volatile("cp.async.wait_group 0;" ::: "memory");
        else             asm volatile("cp.async.wait_group 1;" ::: "memory");
        __syncthreads();
        if (s + 2 < NK) issue(s + 2);

        const uint32_t Ab = smb + (uint32_t)((s % GSTG) * 2 * TILEW) * 4;
        const uint32_t Wb = Ab + TILEW * 4;

#pragma unroll
        for (int ks = 0; ks < 4; ks++) {
            const int chunk = 2 * ks + (lane >> 4);
            uint32_t af[2][4], bf[8][2];
#pragma unroll
            for (int mt = 0; mt < 2; mt++) {
                const int row = wm * 32 + mt * 16 + (lane & 15);
                ldsm4(sw_addr(Ab, row, chunk), af[mt][0], af[mt][1], af[mt][2], af[mt][3]);
            }
#pragma unroll
            for (int ntp = 0; ntp < 4; ntp++) {
                const int row = wn * 64 + ntp * 16 + (lane & 15);
                uint32_t r0, r1, r2, r3;
                ldsm4(sw_addr(Wb, row, chunk), r0, r1, r2, r3);
                bf[2*ntp][0]   = r0; bf[2*ntp][1]   = r2;
                bf[2*ntp+1][0] = r1; bf[2*ntp+1][1] = r3;
            }
#pragma unroll
            for (int mt = 0; mt < 2; mt++)
#pragma unroll
                for (int nt = 0; nt < 8; nt++)
                    mma_f16(c[mt][nt], af[mt], bf[nt]);
        }
    }

    const int g  = lane >> 2;
    const int kq = lane & 3;

    if (outmode < 3) {
        uint32_t* dst = (outmode == 0) ? g_q16 : (outmode == 1) ? g_k16 : g_v16;
        const float qs = (outmode == 0) ? 0.125f : 1.f;
#pragma unroll
        for (int mt = 0; mt < 2; mt++) {
            const int r0 = m0 + wm * 32 + mt * 16 + g;
#pragma unroll
            for (int nt = 0; nt < 8; nt++) {
                const int n  = n0 + wn * 64 + nt * 8 + (kq << 1);
                const float b0 = bias[n], b1 = bias[n + 1];
                const int h  = n >> 6;
                const int hw = (n & 63) >> 1;
#pragma unroll
                for (int half = 0; half < 2; half++) {
                    const int r = r0 + half * 8;
                    const int b = r >> 11;
                    const int s = r & (SS - 1);
                    const float v0 = (c[mt][nt][half * 2 + 0] + b0) * qs;
                    const float v1 = (c[mt][nt][half * 2 + 1] + b1) * qs;
                    dst[(((size_t)(b * HH + h)) * SS + s) * HDW + hw] = packh2(v0, v1);
                }
            }
        }
    } else {
#pragma unroll
        for (int mt = 0; mt < 2; mt++) {
            const int r0 = m0 + wm * 32 + mt * 16 + g;
#pragma unroll
            for (int nt = 0; nt < 8; nt++) {
                const int n  = n0 + wn * 64 + nt * 8 + (kq << 1);
                const float b0 = bias[n], b1 = bias[n + 1];
#pragma unroll
                for (int half = 0; half < 2; half++) {
                    const int r = r0 + half * 8;
                    float2* p = (float2*)&Cext[(size_t)r * DD + n];
                    *p = make_float2(c[mt][nt][half * 2 + 0] + b0,
                                     c[mt][nt][half * 2 + 1] + b1);
                }
            }
        }
    }
}

// ---------------------------------------------------------------------------
// FP16 tensor-core causal flash attention.
// Grid: (S/64, B*H). Block: 128 thr = 4 warps x 16 q-rows.
// K/V tiles 64x64 fp16 (64 rows x 8 chunks, XOR swizzle), double-buffered.
// Q pre-scaled by 1/8. P C->A layout needs NO shuffles in fp16 k16 layout.
// V B-fragments via ldmatrix.x4.trans.
// ---------------------------------------------------------------------------
__global__ void __launch_bounds__(128) attn_f16()
{
    extern __shared__ uint32_t sm[];   // 2 bufs * (K 2048w | V 2048w) = 8192 words
    const uint32_t smb = smem_u32(sm);

    const int bh   = blockIdx.y;
    const int qt   = (gridDim.x - 1) - blockIdx.x;  // heavy tiles first
    const int tid  = threadIdx.x;
    const int lane = tid & 31;
    const int warp = tid >> 5;
    const int g    = lane >> 2;
    const int kq   = lane & 3;

    const uint32_t* Qw = g_q16 + (size_t)bh * SS * HDW;
    const uint32_t* Kw = g_k16 + (size_t)bh * SS * HDW;
    const uint32_t* Vw = g_v16 + (size_t)bh * SS * HDW;

    // ---- stage Q tile (64 x 32 words) into buf0, extract A-fragments ----
#pragma unroll
    for (int i = 0; i < 4; i++) {
        const int idx = tid + i * 128;       // 0..511 chunks
        const int row = idx >> 3;
        const int c4  = idx & 7;
        uint4 f = *(const uint4*)(Qw + ((size_t)qt * 64 + row) * HDW + c4 * 4);
        *(uint4*)(sm + row * 32 + ((c4 ^ (row & 7)) << 2)) = f;
    }
    __syncthreads();

    uint32_t qa[4][4];
#pragma unroll
    for (int ks = 0; ks < 4; ks++) {
        const int row   = warp * 16 + (lane & 15);
        const int chunk = 2 * ks + (lane >> 4);
        ldsm4(sw_addr(smb, row, chunk), qa[ks][0], qa[ks][1], qa[ks][2], qa[ks][3]);
    }
    __syncthreads();

    auto issue_kv = [&](int kt, int buf) {
        const uint32_t kb = smb + (uint32_t)buf * 16384;
#pragma unroll
        for (int i = 0; i < 4; i++) {
            const int idx = tid + i * 128;
            const int row = idx >> 3;
            const int c4  = idx & 7;
            const uint32_t sd = (uint32_t)(row * 128 + ((c4 ^ (row & 7)) << 4));
            const size_t go = ((size_t)kt * 64 + row) * HDW + c4 * 4;
            cpa16s(kb + sd,        Kw + go);
            cpa16s(kb + 8192 + sd, Vw + go);
        }
        asm volatile("cp.async.commit_group;" ::: "memory");
    };

    issue_kv(0, 0);

    float acc[8][4];
#pragma unroll
    for (int nt = 0; nt < 8; nt++)
#pragma unroll
        for (int i = 0; i < 4; i++) acc[nt][i] = 0.f;
    float m0 = -1e30f, m1 = -1e30f, l0 = 0.f, l1 = 0.f;

    const int row0  = warp * 16 + g;
    const int rowg0 = qt * 64 + row0;

    for (int kt = 0; kt <= qt; kt++) {
        asm volatile("cp.async.wait_group 0;" ::: "memory");
        __syncthreads();
        if (kt + 1 <= qt) issue_kv(kt + 1, (kt + 1) & 1);

        const uint32_t Kb = smb + (uint32_t)(kt & 1) * 16384;
        const uint32_t Vb = Kb + 8192;

        // ---- S = Q @ K^T (scale pre-folded into Q) ----
        float c[8][4];
#pragma unroll
        for (int nt = 0; nt < 8; nt++)
#pragma unroll
            for (int i = 0; i < 4; i++) c[nt][i] = 0.f;

#pragma unroll
        for (int ks = 0; ks < 4; ks++) {
            const int chunk = 2 * ks + (lane >> 4);
#pragma unroll
            for (int ntp = 0; ntp < 4; ntp++) {
                const int row = ntp * 16 + (lane & 15);
                uint32_t r0, r1, r2, r3;
                ldsm4(sw_addr(Kb, row, chunk), r0, r1, r2, r3);
                uint32_t kf0[2] = {r0, r2};
                uint32_t kf1[2] = {r1, r3};
                mma_f16(c[2*ntp],   qa[ks], kf0);
                mma_f16(c[2*ntp+1], qa[ks], kf1);
            }
        }

        // ---- causal mask ----
        const bool diag = (kt == qt);
        if (diag) {
#pragma unroll
            for (int nt = 0; nt < 8; nt++) {
                const int colb = kt * 64 + nt * 8 + (kq << 1);
#pragma unroll
                for (int i = 0; i < 4; i++) {
                    const int col = colb + (i & 1);
                    const int row = rowg0 + ((i & 2) << 2);
                    if (col > row) c[nt][i] = -1e30f;
                }
            }
        }

        // ---- online softmax ----
        float t0 = -1e30f, t1 = -1e30f;
#pragma unroll
        for (int nt = 0; nt < 8; nt++) {
            t0 = fmaxf(t0, fmaxf(c[nt][0], c[nt][1]));
            t1 = fmaxf(t1, fmaxf(c[nt][2], c[nt][3]));
        }
        t0 = fmaxf(t0, __shfl_xor_sync(0xffffffffu, t0, 1));
        t0 = fmaxf(t0, __shfl_xor_sync(0xffffffffu, t0, 2));
        t1 = fmaxf(t1, __shfl_xor_sync(0xffffffffu, t1, 1));
        t1 = fmaxf(t1, __shfl_xor_sync(0xffffffffu, t1, 2));

        const float mn0 = fmaxf(m0, t0);
        const float mn1 = fmaxf(m1, t1);
        const float a0  = __expf(m0 - mn0);
        const float a1  = __expf(m1 - mn1);

        float s0 = 0.f, s1 = 0.f;
#pragma unroll
        for (int nt = 0; nt < 8; nt++) {
            c[nt][0] = __expf(c[nt][0] - mn0);
            c[nt][1] = __expf(c[nt][1] - mn0);
            c[nt][2] = __expf(c[nt][2] - mn1);
            c[nt][3] = __expf(c[nt][3] - mn1);
            s0 += c[nt][0] + c[nt][1];
            s1 += c[nt][2] + c[nt][3];
        }
        s0 += __shfl_xor_sync(0xffffffffu, s0, 1);
        s0 += __shfl_xor_sync(0xffffffffu, s0, 2);
        s1 += __shfl_xor_sync(0xffffffffu, s1, 1);
        s1 += __shfl_xor_sync(0xffffffffu, s1, 2);

        l0 = l0 * a0 + s0;  m0 = mn0;
        l1 = l1 * a1 + s1;  m1 = mn1;

#pragma unroll
        for (int nt = 0; nt < 8; nt++) {
            acc[nt][0] *= a0; acc[nt][1] *= a0;
            acc[nt][2] *= a1; acc[nt][3] *= a1;
        }

        // ---- O += P @ V : P packs directly into A-fragments (no shuffles) ----
#pragma unroll
        for (int ksp = 0; ksp < 4; ksp++) {
            uint32_t pa[4];
            pa[0] = packh2(c[2*ksp][0],   c[2*ksp][1]);
            pa[1] = packh2(c[2*ksp][2],   c[2*ksp][3]);
            pa[2] = packh2(c[2*ksp+1][0], c[2*ksp+1][1]);
            pa[3] = packh2(c[2*ksp+1][2], c[2*ksp+1][3]);
#pragma unroll
            for (int ntp = 0; ntp < 4; ntp++) {
                const int row   = 16 * ksp + (lane & 15);
                const int chunk = 2 * ntp + (lane >> 4);
                uint32_t r0, r1, r2, r3;
                ldsm4t(sw_addr(Vb, row, chunk), r0, r1, r2, r3);
                uint32_t vb0[2] = {r0, r1};
                uint32_t vb1[2] = {r2, r3};
                mma_f16(acc[2*ntp],   pa, vb0);
                mma_f16(acc[2*ntp+1], pa, vb1);
            }
        }
    }

    // ---- finalize: normalize, pack fp16, store [B,S,D] ----
    const int b = bh >> 4, h = bh & 15;
    const float inv0 = 1.f / l0;
    const float inv1 = 1.f / l1;
    const int qr0 = qt * 64 + row0;
    const int qr1 = qr0 + 8;
#pragma unroll
    for (int nt = 0; nt < 8; nt++) {
        const int word = h * 32 + nt * 4 + kq;   // (h*64 + nt*8 + 2kq)/2
        g_attn16[((size_t)(b * SS + qr0)) * (DD/2) + word] =
            packh2(acc[nt][0] * inv0, acc[nt][1] * inv0);
        g_attn16[((size_t)(b * SS + qr1)) * (DD/2) + word] =
            packh2(acc[nt][2] * inv1, acc[nt][3] * inv1);
    }
}

// ---------------------------------------------------------------------------
extern "C" void kernel_launch(void* const* d_in, const int* in_sizes, int n_in,
                              void* d_out, int out_size)
{
    const float* x  = (const float*)d_in[0];
    const float* qw = (const float*)d_in[1];
    const float* qb = (const float*)d_in[2];
    const float* kw = (const float*)d_in[3];
    const float* kb = (const float*)d_in[4];
    const float* vw = (const float*)d_in[5];
    const float* vb = (const float*)d_in[6];
    const float* ow = (const float*)d_in[7];
    const float* ob = (const float*)d_in[8];
    float* out = (float*)d_out;

    const int gemm_smem = GSTG * 2 * TILEW * (int)sizeof(uint32_t);  // 96 KB
    const int attn_smem = 8192 * (int)sizeof(uint32_t);              // 32 KB
    cudaFuncSetAttribute(gemm_f16, cudaFuncAttributeMaxDynamicSharedMemorySize, gemm_smem);

    prep_f16<<<(MDIM + 4 * DD) * (KD / 8) / 256, 256>>>(x, qw, kw, vw, ow);

    // fused QKV: z selects outmode
    gemm_f16<<<dim3(DD / 128, MDIM / 128, 3), 256, gemm_smem>>>(qb, kb, vb, nullptr, -1);

    attn_f16<<<dim3(SS / 64, BB * HH), 128, attn_smem>>>();

    gemm_f16<<<dim3(DD / 128, MDIM / 128, 1), 256, gemm_smem>>>(ob, ob, ob, out, 3);
}